// round 10
// baseline (speedup 1.0000x reference)
#include <cuda_runtime.h>
#include <cuda_bf16.h>

#define VSZ 32000
#define HSZ 256
#define BSZ 256
#define SSZ 512

typedef unsigned long long ull;

// Scratch (device globals; no allocation allowed)
__device__ float g_eproj[(size_t)VSZ * 768];   // emb @ [Wz;Wr;Wh]^T + biases
__device__ float g_hlast[BSZ * HSZ];
// Transposed packed U, k-grouped for uint4 loads. Each 32-bit word holds
// lo-column bf16 in [15:0] and a COMPENSATED hi field in [31:16]: the word
// interpreted directly as f32 is the nearest value to the true hi-column
// weight given the fixed low bits (error <= 1/2 bf16 ulp). Kernel expansion:
// lo = word<<16, hi = word (no AND needed).
__device__ uint4 g_zr4[128 * 128];
__device__ uint4 g_uh4[64 * 128];

// ---- packed f32x2 helpers (Blackwell sm_103a) ----
__device__ __forceinline__ ull pk2(float lo, float hi) {
    ull r;
    asm("mov.b64 %0, {%1, %2};" : "=l"(r) : "f"(lo), "f"(hi));
    return r;
}
__device__ __forceinline__ void fma2(ull& d, ull a, ull b) {
    asm("fma.rn.f32x2 %0, %1, %2, %0;" : "+l"(d) : "l"(a), "l"(b));
}
__device__ __forceinline__ ull addf2(ull a, ull b) {
    ull r;
    asm("add.rn.f32x2 %0, %1, %2;" : "=l"(r) : "l"(a), "l"(b));
    return r;
}
__device__ __forceinline__ ull bflyadd(ull v) {
    v = addf2(v, __shfl_xor_sync(0xffffffffu, v, 8));
    v = addf2(v, __shfl_xor_sync(0xffffffffu, v, 16));
    return v;
}
__device__ __forceinline__ float pick(ull v, int hi_sel) {
    float lo, hi;
    asm("mov.b64 {%0, %1}, %2;" : "=f"(lo), "=f"(hi) : "l"(v));
    return hi_sel ? hi : lo;
}
// compensated expansion: lo = word<<16, hi = word used directly (1 ALU op)
__device__ __forceinline__ ull bf2f2c(unsigned v) {
    ull r;
    asm("{\n\t.reg .b32 lo;\n\t"
        "shl.b32 lo, %1, 16;\n\t"
        "mov.b64 %0, {lo, %1};\n\t}" : "=l"(r) : "r"(v));
    return r;
}
__device__ __forceinline__ float fast_sigm(float x) {
    float e, r;
    asm("ex2.approx.ftz.f32 %0, %1;" : "=f"(e) : "f"(-1.4426950408889634f * x));
    asm("rcp.approx.ftz.f32 %0, %1;" : "=f"(r) : "f"(1.0f + e));
    return r;
}
__device__ __forceinline__ float fast_tanh(float x) {
    float r;
    asm("tanh.approx.f32 %0, %1;" : "=f"(r) : "f"(x));
    return r;
}
// compensated pack: lo = round-nearest bf16(lo_w); hi field chosen so the
// full word-as-f32 is nearest to hi_w given fixed low bits.
__device__ __forceinline__ unsigned pkcomp(float lo_w, float hi_w) {
    unsigned lo = (unsigned)__bfloat16_as_ushort(__float2bfloat16(lo_w));
    unsigned bits = __float_as_uint(hi_w);
    long long d = (long long)bits - (long long)lo;
    long long h = (d + 32768LL) >> 16;
    if (h < 0) h = 0;
    if (h > 65535) h = 65535;
    return ((unsigned)h << 16) | lo;
}

// ============================================================================
// Pack U into transposed compensated streams
// ============================================================================
__global__ void pack_u(const float* __restrict__ Uz, const float* __restrict__ Ur,
                       const float* __restrict__ Uh)
{
    const int k2 = blockIdx.x;     // 0..127
    const int jg = threadIdx.x;    // 0..127
    const int j0 = 2 * jg;
    const int ka = 2 * k2, kb = 2 * k2 + 1;
    uint4 v;
    v.x = pkcomp(Uz[j0 * 256 + ka], Uz[(j0 + 1) * 256 + ka]);
    v.y = pkcomp(Ur[j0 * 256 + ka], Ur[(j0 + 1) * 256 + ka]);
    v.z = pkcomp(Uz[j0 * 256 + kb], Uz[(j0 + 1) * 256 + kb]);
    v.w = pkcomp(Ur[j0 * 256 + kb], Ur[(j0 + 1) * 256 + kb]);
    g_zr4[k2 * 128 + jg] = v;
    if (k2 < 64) {
        const int kc = 4 * k2;
        uint4 h;
        h.x = pkcomp(Uh[j0 * 256 + kc],     Uh[(j0 + 1) * 256 + kc]);
        h.y = pkcomp(Uh[j0 * 256 + kc + 1], Uh[(j0 + 1) * 256 + kc + 1]);
        h.z = pkcomp(Uh[j0 * 256 + kc + 2], Uh[(j0 + 1) * 256 + kc + 2]);
        h.w = pkcomp(Uh[j0 * 256 + kc + 3], Uh[(j0 + 1) * 256 + kc + 3]);
        g_uh4[k2 * 128 + jg] = h;
    }
}

// ============================================================================
// SGEMM-NT with bias (~90% of scalar f32x2 floor)
// ============================================================================
__global__ void __launch_bounds__(256) sgemm_nt_bias(
    const float* __restrict__ A, const float* __restrict__ Bw,
    const float* __restrict__ bias1, const float* __restrict__ bias2,
    float* __restrict__ C, int ldc, int coloff)
{
    __shared__ __align__(16) float As[16][132];
    __shared__ __align__(16) float Bs[16][132];
    const int t  = threadIdx.x;
    const int tm = t >> 4;
    const int tn = t & 15;

    ull acc[8][4];
#pragma unroll
    for (int i = 0; i < 8; i++)
#pragma unroll
        for (int j = 0; j < 4; j++) acc[i][j] = 0ULL;

    const float* Ab = A  + (size_t)blockIdx.x * 128 * 256;
    const float* Bb = Bw + (size_t)blockIdx.y * 128 * 256;
    const int lr = t >> 2;
    const int lk = (t & 3) << 2;

    for (int k0 = 0; k0 < 256; k0 += 16) {
        float4 a0 = *(const float4*)(Ab + (size_t)lr * 256 + k0 + lk);
        float4 a1 = *(const float4*)(Ab + (size_t)(lr + 64) * 256 + k0 + lk);
        float4 b0 = *(const float4*)(Bb + (size_t)lr * 256 + k0 + lk);
        float4 b1 = *(const float4*)(Bb + (size_t)(lr + 64) * 256 + k0 + lk);
        __syncthreads();
        As[lk + 0][lr] = a0.x; As[lk + 1][lr] = a0.y;
        As[lk + 2][lr] = a0.z; As[lk + 3][lr] = a0.w;
        As[lk + 0][lr + 64] = a1.x; As[lk + 1][lr + 64] = a1.y;
        As[lk + 2][lr + 64] = a1.z; As[lk + 3][lr + 64] = a1.w;
        Bs[lk + 0][lr] = b0.x; Bs[lk + 1][lr] = b0.y;
        Bs[lk + 2][lr] = b0.z; Bs[lk + 3][lr] = b0.w;
        Bs[lk + 0][lr + 64] = b1.x; Bs[lk + 1][lr + 64] = b1.y;
        Bs[lk + 2][lr + 64] = b1.z; Bs[lk + 3][lr + 64] = b1.w;
        __syncthreads();
#pragma unroll
        for (int kk = 0; kk < 16; kk++) {
            float4 av0 = *(const float4*)(&As[kk][tm * 8]);
            float4 av1 = *(const float4*)(&As[kk][tm * 8 + 4]);
            const ull* bp = (const ull*)(&Bs[kk][tn * 8]);
            ull b2_0 = bp[0], b2_1 = bp[1], b2_2 = bp[2], b2_3 = bp[3];
            float av[8] = {av0.x, av0.y, av0.z, av0.w, av1.x, av1.y, av1.z, av1.w};
#pragma unroll
            for (int i = 0; i < 8; i++) {
                ull a2 = pk2(av[i], av[i]);
                fma2(acc[i][0], a2, b2_0);
                fma2(acc[i][1], a2, b2_1);
                fma2(acc[i][2], a2, b2_2);
                fma2(acc[i][3], a2, b2_3);
            }
        }
    }

    const int row0 = blockIdx.x * 128 + tm * 8;
    const int col0 = blockIdx.y * 128 + tn * 8;
#pragma unroll
    for (int i = 0; i < 8; i++) {
#pragma unroll
        for (int j = 0; j < 4; j++) {
            float lo, hi;
            asm("mov.b64 {%0, %1}, %2;" : "=f"(lo), "=f"(hi) : "l"(acc[i][j]));
            int n0 = col0 + j * 2;
            float e0 = bias1[n0]     + (bias2 ? bias2[n0]     : 0.0f);
            float e1 = bias1[n0 + 1] + (bias2 ? bias2[n0 + 1] : 0.0f);
            C[(size_t)(row0 + i) * ldc + coloff + n0]     = lo + e0;
            C[(size_t)(row0 + i) * ldc + coloff + n0 + 1] = hi + e1;
        }
    }
}

// ============================================================================
// GRU scan v10: exact v8 structure (column-pinned, warp-butterfly) +
// compensated single-SHL expansion + deeper phase-1 global ring (12).
// ============================================================================
#define SCAN_SM_BYTES 204928

#define P1BODY(u, hb, kk)                                                   \
    {                                                                       \
        ull uz0 = bf2f2c((u).x), ur0 = bf2f2c((u).y);                       \
        ull uz1 = bf2f2c((u).z), ur1 = bf2f2c((u).w);                       \
        ulonglong2 h0 = *(const ulonglong2*)(hdup + (hb) + 4 * (kk));       \
        ulonglong2 h1 = *(const ulonglong2*)(hdup + (hb) + 4 * (kk) + 2);   \
        fma2(az0, uz0, h0.x); fma2(az1, uz0, h0.y);                         \
        fma2(ar0, ur0, h0.x); fma2(ar1, ur0, h0.y);                         \
        fma2(az0, uz1, h1.x); fma2(az1, uz1, h1.y);                         \
        fma2(ar0, ur1, h1.x); fma2(ar1, ur1, h1.y);                         \
    }

#define P2BODY(u, sb, kk)                                                   \
    {                                                                       \
        ull uh0 = bf2f2c((u).x), uh1 = bf2f2c((u).y);                       \
        ull uh2 = bf2f2c((u).z), uh3 = bf2f2c((u).w);                       \
        ulonglong2 s0 = *(const ulonglong2*)(srhdup + (sb) + 8 * (kk));     \
        ulonglong2 s1 = *(const ulonglong2*)(srhdup + (sb) + 8 * (kk) + 2); \
        ulonglong2 s2 = *(const ulonglong2*)(srhdup + (sb) + 8 * (kk) + 4); \
        ulonglong2 s3 = *(const ulonglong2*)(srhdup + (sb) + 8 * (kk) + 6); \
        fma2(ah0, uh0, s0.x); fma2(ah1, uh0, s0.y);                         \
        fma2(ah0, uh1, s1.x); fma2(ah1, uh1, s1.y);                         \
        fma2(ah0, uh2, s2.x); fma2(ah1, uh2, s2.y);                         \
        fma2(ah0, uh3, s3.x); fma2(ah1, uh3, s3.y);                         \
    }

__global__ void __launch_bounds__(512, 1) gru_scan10(const int* __restrict__ x)
{
    extern __shared__ __align__(16) char smraw[];
    uint4* pin_zr4 = (uint4*)smraw;                   // [k2<128][jg<64] 131072 B
    uint4* pin_uh4 = (uint4*)(smraw + 131072);        // [k4<64][jg<64]   65536 B
    ull*   hdup    = (ull*)(smraw + 196608);          // 520 ull, padded
    ull*   srhdup  = (ull*)(smraw + 200768);          // 520 ull, padded

    const int t    = threadIdx.x;
    const int lane = t & 31;
    const int w    = t >> 5;
    const int jp   = (w << 3) | (lane & 7);   // col-pair 0..127
    const int kh   = lane >> 3;               // 0..3
    const int row  = kh & 1;
    const int csel = kh >> 1;
    const int mycol = (jp << 1) | csel;
    const int b0   = blockIdx.x * 2;
    const bool smw = (w < 8);                 // uniform per warp

    // ---- pin columns jg<64 + zero padded state ----
    for (int i = t; i < 128 * 64; i += 512)
        pin_zr4[i] = g_zr4[(i >> 6) * 128 + (i & 63)];
    for (int i = t; i < 64 * 64; i += 512)
        pin_uh4[i] = g_uh4[(i >> 6) * 128 + (i & 63)];
    for (int i = t; i < 520; i += 512) { hdup[i] = 0ULL; srhdup[i] = 0ULL; }
    __syncthreads();

    // per-warp-uniform stream bases (k2 base = kh*32; k4 base = kh*16)
    const uint4* zsP = pin_zr4 + (kh * 32) * 64 + jp;        // smem, stride 64
    const uint4* zgP = g_zr4   + (kh * 32) * 128 + jp;       // gmem, stride 128
    const uint4* hsP = pin_uh4 + (kh * 16) * 64 + jp;
    const uint4* hgP = g_uh4   + (kh * 16) * 128 + jp;
    const int hb = 130 * kh;   // padded ull base for this kh's 64-k block

    // global register rings (only live for global warps); non-pow2 sizes are
    // fine: all indices fold at compile time under full unroll
    uint4 zr_ring[12], uh_ring[4];
    if (!smw) {
#pragma unroll
        for (int i = 0; i < 12; i++) zr_ring[i] = zgP[i * 128];
#pragma unroll
        for (int i = 0; i < 4; i++) uh_ring[i] = hgP[i * 128];
    }

    // lane-owned state + e/token pipeline
    float hold = 0.0f, zg = 0.0f;
    const int xrow = (b0 + row) * SSZ;
    const int wc = 2 * mycol + row + ((mycol >> 6) << 1);   // padded state idx
    int tok = __ldg(&x[xrow]);
    const float* e0 = g_eproj + (size_t)tok * 768;
    float ez = __ldg(e0 + mycol);
    float er = __ldg(e0 + 256 + mycol);
    float eh = __ldg(e0 + 512 + mycol);
    int tok1 = __ldg(&x[xrow + 1]);

    for (int s = 0; s < SSZ; s++) {
        // ================= phase 1: z, r partials (64 k) =================
        ull az0 = 0, az1 = 0, ar0 = 0, ar1 = 0;
        if (smw) {
#pragma unroll
            for (int kk = 0; kk < 32; kk++) {
                uint4 u = zsP[kk * 64];
                P1BODY(u, hb, kk);
            }
        } else {
#pragma unroll
            for (int kk = 0; kk < 32; kk++) {
                uint4 u = zr_ring[kk % 12];
                zr_ring[kk % 12] = zgP[((kk + 12) & 31) * 128];
                P1BODY(u, hb, kk);
            }
        }
        az0 = bflyadd(az0); az1 = bflyadd(az1);
        ar0 = bflyadd(ar0); ar1 = bflyadd(ar1);

        const float sz = pick(row ? az1 : az0, csel);
        const float sr = pick(row ? ar1 : ar0, csel);
        zg = fast_sigm(sz + ez);
        const float rg = fast_sigm(sr + er);
        const float rh = rg * hold;
        srhdup[wc] = pk2(rh, rh);
        const float* en = g_eproj + (size_t)tok1 * 768;
        ez = __ldg(en + mycol);
        er = __ldg(en + 256 + mycol);
        __syncthreads();

        // ================= phase 2: h_tilde partials (64 k) =================
        ull ah0 = 0, ah1 = 0;
        if (smw) {
#pragma unroll
            for (int kk = 0; kk < 16; kk++) {
                uint4 u = hsP[kk * 64];
                P2BODY(u, hb, kk);
            }
        } else {
#pragma unroll
            for (int kk = 0; kk < 16; kk++) {
                uint4 u = uh_ring[kk & 3];
                uh_ring[kk & 3] = hgP[((kk + 4) & 15) * 128];
                P2BODY(u, hb, kk);
            }
        }
        ah0 = bflyadd(ah0); ah1 = bflyadd(ah1);

        const float sh = pick(row ? ah1 : ah0, csel);
        const float ht = fast_tanh(sh + eh);
        hold += zg * (ht - hold);
        hdup[wc] = pk2(hold, hold);
        eh = __ldg(en + 512 + mycol);
        {
            int s2 = (s + 2 < SSZ) ? s + 2 : SSZ - 1;
            tok1 = __ldg(&x[xrow + s2]);
        }
        __syncthreads();
    }

    g_hlast[(size_t)(b0 + row) * HSZ + mycol] = hold;
}

// ============================================================================
extern "C" void kernel_launch(void* const* d_in, const int* in_sizes, int n_in,
                              void* d_out, int out_size)
{
    const int*   x   = (const int*)  d_in[0];
    const float* emb = (const float*)d_in[1];
    const float* Wz  = (const float*)d_in[2];
    const float* bz  = (const float*)d_in[3];
    const float* Uz  = (const float*)d_in[4];
    const float* buz = (const float*)d_in[5];
    const float* Wr  = (const float*)d_in[6];
    const float* br  = (const float*)d_in[7];
    const float* Ur  = (const float*)d_in[8];
    const float* bur = (const float*)d_in[9];
    const float* Wh  = (const float*)d_in[10];
    const float* bh  = (const float*)d_in[11];
    const float* Uh  = (const float*)d_in[12];
    const float* buh = (const float*)d_in[13];
    const float* Wf  = (const float*)d_in[14];
    const float* bf  = (const float*)d_in[15];
    float* out = (float*)d_out;

    float* eproj = nullptr;
    float* hlast = nullptr;
    cudaGetSymbolAddress((void**)&eproj, g_eproj);
    cudaGetSymbolAddress((void**)&hlast, g_hlast);

    cudaFuncSetAttribute(gru_scan10,
                         cudaFuncAttributeMaxDynamicSharedMemorySize, SCAN_SM_BYTES);

    dim3 blk(256);
    pack_u<<<128, 128>>>(Uz, Ur, Uh);
    sgemm_nt_bias<<<dim3(250, 2), blk>>>(emb, Wz, bz, buz, eproj, 768, 0);
    sgemm_nt_bias<<<dim3(250, 2), blk>>>(emb, Wr, br, bur, eproj, 768, 256);
    sgemm_nt_bias<<<dim3(250, 2), blk>>>(emb, Wh, bh, buh, eproj, 768, 512);

    gru_scan10<<<128, 512, SCAN_SM_BYTES>>>(x);

    sgemm_nt_bias<<<dim3(2, 250), blk>>>(hlast, Wf, bf, nullptr, out, 32000, 0);
}

// round 11
// speedup vs baseline: 1.0277x; 1.0277x over previous
#include <cuda_runtime.h>
#include <cuda_bf16.h>

#define VSZ 32000
#define HSZ 256
#define BSZ 256
#define SSZ 512

typedef unsigned long long ull;

// Scratch (device globals; no allocation allowed)
__device__ float g_eproj[(size_t)VSZ * 768];   // emb @ [Wz;Wr;Wh]^T + biases
__device__ float g_hlast[BSZ * HSZ];
// Transposed packed U, k-grouped for uint4 loads. Each 32-bit word holds
// lo-column bf16 in [15:0] and a COMPENSATED hi field in [31:16]: the word
// interpreted directly as f32 is the nearest value to the true hi-column
// weight given the fixed low bits (error <= 1/2 bf16 ulp each). Expansion:
// lo = word<<16, hi = word itself (single SHL; no AND).
__device__ uint4 g_zr4[128 * 128];
__device__ uint4 g_uh4[64 * 128];

// ---- packed f32x2 helpers (Blackwell sm_103a) ----
__device__ __forceinline__ ull pk2(float lo, float hi) {
    ull r;
    asm("mov.b64 %0, {%1, %2};" : "=l"(r) : "f"(lo), "f"(hi));
    return r;
}
__device__ __forceinline__ void fma2(ull& d, ull a, ull b) {
    asm("fma.rn.f32x2 %0, %1, %2, %0;" : "+l"(d) : "l"(a), "l"(b));
}
__device__ __forceinline__ ull addf2(ull a, ull b) {
    ull r;
    asm("add.rn.f32x2 %0, %1, %2;" : "=l"(r) : "l"(a), "l"(b));
    return r;
}
__device__ __forceinline__ ull bflyadd(ull v) {
    v = addf2(v, __shfl_xor_sync(0xffffffffu, v, 8));
    v = addf2(v, __shfl_xor_sync(0xffffffffu, v, 16));
    return v;
}
__device__ __forceinline__ float pick(ull v, int hi_sel) {
    float lo, hi;
    asm("mov.b64 {%0, %1}, %2;" : "=f"(lo), "=f"(hi) : "l"(v));
    return hi_sel ? hi : lo;
}
// compensated expansion: lo = word<<16, hi = word used directly (1 ALU op)
__device__ __forceinline__ ull bf2f2c(unsigned v) {
    ull r;
    asm("{\n\t.reg .b32 lo;\n\t"
        "shl.b32 lo, %1, 16;\n\t"
        "mov.b64 %0, {lo, %1};\n\t}" : "=l"(r) : "r"(v));
    return r;
}
__device__ __forceinline__ float fast_sigm(float x) {
    float e, r;
    asm("ex2.approx.ftz.f32 %0, %1;" : "=f"(e) : "f"(-1.4426950408889634f * x));
    asm("rcp.approx.ftz.f32 %0, %1;" : "=f"(r) : "f"(1.0f + e));
    return r;
}
__device__ __forceinline__ float fast_tanh(float x) {
    float r;
    asm("tanh.approx.f32 %0, %1;" : "=f"(r) : "f"(x));
    return r;
}
// compensated pack: lo = round-nearest bf16(lo_w); hi field chosen so the
// full word-as-f32 is nearest to hi_w given fixed low bits.
__device__ __forceinline__ unsigned pkcomp(float lo_w, float hi_w) {
    unsigned lo = (unsigned)__bfloat16_as_ushort(__float2bfloat16(lo_w));
    unsigned bits = __float_as_uint(hi_w);
    long long d = (long long)bits - (long long)lo;
    long long h = (d + 32768LL) >> 16;
    if (h < 0) h = 0;
    if (h > 65535) h = 65535;
    return ((unsigned)h << 16) | lo;
}

// ============================================================================
// Pack U into transposed compensated streams
// ============================================================================
__global__ void pack_u(const float* __restrict__ Uz, const float* __restrict__ Ur,
                       const float* __restrict__ Uh)
{
    const int k2 = blockIdx.x;     // 0..127
    const int jg = threadIdx.x;    // 0..127
    const int j0 = 2 * jg;
    const int ka = 2 * k2, kb = 2 * k2 + 1;
    uint4 v;
    v.x = pkcomp(Uz[j0 * 256 + ka], Uz[(j0 + 1) * 256 + ka]);
    v.y = pkcomp(Ur[j0 * 256 + ka], Ur[(j0 + 1) * 256 + ka]);
    v.z = pkcomp(Uz[j0 * 256 + kb], Uz[(j0 + 1) * 256 + kb]);
    v.w = pkcomp(Ur[j0 * 256 + kb], Ur[(j0 + 1) * 256 + kb]);
    g_zr4[k2 * 128 + jg] = v;
    if (k2 < 64) {
        const int kc = 4 * k2;
        uint4 h;
        h.x = pkcomp(Uh[j0 * 256 + kc],     Uh[(j0 + 1) * 256 + kc]);
        h.y = pkcomp(Uh[j0 * 256 + kc + 1], Uh[(j0 + 1) * 256 + kc + 1]);
        h.z = pkcomp(Uh[j0 * 256 + kc + 2], Uh[(j0 + 1) * 256 + kc + 2]);
        h.w = pkcomp(Uh[j0 * 256 + kc + 3], Uh[(j0 + 1) * 256 + kc + 3]);
        g_uh4[k2 * 128 + jg] = h;
    }
}

// ============================================================================
// SGEMM-NT with bias (~90% of scalar f32x2 floor)
// ============================================================================
__global__ void __launch_bounds__(256) sgemm_nt_bias(
    const float* __restrict__ A, const float* __restrict__ Bw,
    const float* __restrict__ bias1, const float* __restrict__ bias2,
    float* __restrict__ C, int ldc, int coloff)
{
    __shared__ __align__(16) float As[16][132];
    __shared__ __align__(16) float Bs[16][132];
    const int t  = threadIdx.x;
    const int tm = t >> 4;
    const int tn = t & 15;

    ull acc[8][4];
#pragma unroll
    for (int i = 0; i < 8; i++)
#pragma unroll
        for (int j = 0; j < 4; j++) acc[i][j] = 0ULL;

    const float* Ab = A  + (size_t)blockIdx.x * 128 * 256;
    const float* Bb = Bw + (size_t)blockIdx.y * 128 * 256;
    const int lr = t >> 2;
    const int lk = (t & 3) << 2;

    for (int k0 = 0; k0 < 256; k0 += 16) {
        float4 a0 = *(const float4*)(Ab + (size_t)lr * 256 + k0 + lk);
        float4 a1 = *(const float4*)(Ab + (size_t)(lr + 64) * 256 + k0 + lk);
        float4 b0 = *(const float4*)(Bb + (size_t)lr * 256 + k0 + lk);
        float4 b1 = *(const float4*)(Bb + (size_t)(lr + 64) * 256 + k0 + lk);
        __syncthreads();
        As[lk + 0][lr] = a0.x; As[lk + 1][lr] = a0.y;
        As[lk + 2][lr] = a0.z; As[lk + 3][lr] = a0.w;
        As[lk + 0][lr + 64] = a1.x; As[lk + 1][lr + 64] = a1.y;
        As[lk + 2][lr + 64] = a1.z; As[lk + 3][lr + 64] = a1.w;
        Bs[lk + 0][lr] = b0.x; Bs[lk + 1][lr] = b0.y;
        Bs[lk + 2][lr] = b0.z; Bs[lk + 3][lr] = b0.w;
        Bs[lk + 0][lr + 64] = b1.x; Bs[lk + 1][lr + 64] = b1.y;
        Bs[lk + 2][lr + 64] = b1.z; Bs[lk + 3][lr + 64] = b1.w;
        __syncthreads();
#pragma unroll
        for (int kk = 0; kk < 16; kk++) {
            float4 av0 = *(const float4*)(&As[kk][tm * 8]);
            float4 av1 = *(const float4*)(&As[kk][tm * 8 + 4]);
            const ull* bp = (const ull*)(&Bs[kk][tn * 8]);
            ull b2_0 = bp[0], b2_1 = bp[1], b2_2 = bp[2], b2_3 = bp[3];
            float av[8] = {av0.x, av0.y, av0.z, av0.w, av1.x, av1.y, av1.z, av1.w};
#pragma unroll
            for (int i = 0; i < 8; i++) {
                ull a2 = pk2(av[i], av[i]);
                fma2(acc[i][0], a2, b2_0);
                fma2(acc[i][1], a2, b2_1);
                fma2(acc[i][2], a2, b2_2);
                fma2(acc[i][3], a2, b2_3);
            }
        }
    }

    const int row0 = blockIdx.x * 128 + tm * 8;
    const int col0 = blockIdx.y * 128 + tn * 8;
#pragma unroll
    for (int i = 0; i < 8; i++) {
#pragma unroll
        for (int j = 0; j < 4; j++) {
            float lo, hi;
            asm("mov.b64 {%0, %1}, %2;" : "=f"(lo), "=f"(hi) : "l"(acc[i][j]));
            int n0 = col0 + j * 2;
            float e0 = bias1[n0]     + (bias2 ? bias2[n0]     : 0.0f);
            float e1 = bias1[n0 + 1] + (bias2 ? bias2[n0 + 1] : 0.0f);
            C[(size_t)(row0 + i) * ldc + coloff + n0]     = lo + e0;
            C[(size_t)(row0 + i) * ldc + coloff + n0 + 1] = hi + e1;
        }
    }
}

// ============================================================================
// GRU scan v11: EXACT v8 structure (column-pinned jg<64, warp-butterfly,
// depth-8/4 pow2 rings with verified cross-step masks) + compensated
// single-SHL expansion. Single-variable change vs the 2706us best.
// ============================================================================
#define SCAN_SM_BYTES 204928

#define P1BODY(u, hb, kk)                                                   \
    {                                                                       \
        ull uz0 = bf2f2c((u).x), ur0 = bf2f2c((u).y);                       \
        ull uz1 = bf2f2c((u).z), ur1 = bf2f2c((u).w);                       \
        ulonglong2 h0 = *(const ulonglong2*)(hdup + (hb) + 4 * (kk));       \
        ulonglong2 h1 = *(const ulonglong2*)(hdup + (hb) + 4 * (kk) + 2);   \
        fma2(az0, uz0, h0.x); fma2(az1, uz0, h0.y);                         \
        fma2(ar0, ur0, h0.x); fma2(ar1, ur0, h0.y);                         \
        fma2(az0, uz1, h1.x); fma2(az1, uz1, h1.y);                         \
        fma2(ar0, ur1, h1.x); fma2(ar1, ur1, h1.y);                         \
    }

#define P2BODY(u, sb, kk)                                                   \
    {                                                                       \
        ull uh0 = bf2f2c((u).x), uh1 = bf2f2c((u).y);                       \
        ull uh2 = bf2f2c((u).z), uh3 = bf2f2c((u).w);                       \
        ulonglong2 s0 = *(const ulonglong2*)(srhdup + (sb) + 8 * (kk));     \
        ulonglong2 s1 = *(const ulonglong2*)(srhdup + (sb) + 8 * (kk) + 2); \
        ulonglong2 s2 = *(const ulonglong2*)(srhdup + (sb) + 8 * (kk) + 4); \
        ulonglong2 s3 = *(const ulonglong2*)(srhdup + (sb) + 8 * (kk) + 6); \
        fma2(ah0, uh0, s0.x); fma2(ah1, uh0, s0.y);                         \
        fma2(ah0, uh1, s1.x); fma2(ah1, uh1, s1.y);                         \
        fma2(ah0, uh2, s2.x); fma2(ah1, uh2, s2.y);                         \
        fma2(ah0, uh3, s3.x); fma2(ah1, uh3, s3.y);                         \
    }

__global__ void __launch_bounds__(512, 1) gru_scan11(const int* __restrict__ x)
{
    extern __shared__ __align__(16) char smraw[];
    uint4* pin_zr4 = (uint4*)smraw;                   // [k2<128][jg<64] 131072 B
    uint4* pin_uh4 = (uint4*)(smraw + 131072);        // [k4<64][jg<64]   65536 B
    ull*   hdup    = (ull*)(smraw + 196608);          // 520 ull, padded
    ull*   srhdup  = (ull*)(smraw + 200768);          // 520 ull, padded

    const int t    = threadIdx.x;
    const int lane = t & 31;
    const int w    = t >> 5;
    const int jp   = (w << 3) | (lane & 7);   // col-pair 0..127
    const int kh   = lane >> 3;               // 0..3
    const int row  = kh & 1;
    const int csel = kh >> 1;
    const int mycol = (jp << 1) | csel;
    const int b0   = blockIdx.x * 2;
    const bool smw = (w < 8);                 // uniform per warp

    // ---- pin columns jg<64 + zero padded state ----
    for (int i = t; i < 128 * 64; i += 512)
        pin_zr4[i] = g_zr4[(i >> 6) * 128 + (i & 63)];
    for (int i = t; i < 64 * 64; i += 512)
        pin_uh4[i] = g_uh4[(i >> 6) * 128 + (i & 63)];
    for (int i = t; i < 520; i += 512) { hdup[i] = 0ULL; srhdup[i] = 0ULL; }
    __syncthreads();

    // per-warp-uniform stream bases (k2 base = kh*32; k4 base = kh*16)
    const uint4* zsP = pin_zr4 + (kh * 32) * 64 + jp;        // smem, stride 64
    const uint4* zgP = g_zr4   + (kh * 32) * 128 + jp;       // gmem, stride 128
    const uint4* hsP = pin_uh4 + (kh * 16) * 64 + jp;
    const uint4* hgP = g_uh4   + (kh * 16) * 128 + jp;
    const int hb = 130 * kh;   // padded ull base for this kh's 64-k block

    // global register rings (only live for global warps); pow2 depth with
    // verified cross-step alignment: slot kk&7 <-> refill (kk+8)&31.
    uint4 zr_ring[8], uh_ring[4];
    if (!smw) {
#pragma unroll
        for (int i = 0; i < 8; i++) zr_ring[i] = zgP[i * 128];
#pragma unroll
        for (int i = 0; i < 4; i++) uh_ring[i] = hgP[i * 128];
    }

    // lane-owned state + e/token pipeline
    float hold = 0.0f, zg = 0.0f;
    const int xrow = (b0 + row) * SSZ;
    const int wc = 2 * mycol + row + ((mycol >> 6) << 1);   // padded state idx
    int tok = __ldg(&x[xrow]);
    const float* e0 = g_eproj + (size_t)tok * 768;
    float ez = __ldg(e0 + mycol);
    float er = __ldg(e0 + 256 + mycol);
    float eh = __ldg(e0 + 512 + mycol);
    int tok1 = __ldg(&x[xrow + 1]);

    for (int s = 0; s < SSZ; s++) {
        // ================= phase 1: z, r partials (64 k) =================
        ull az0 = 0, az1 = 0, ar0 = 0, ar1 = 0;
        if (smw) {
#pragma unroll
            for (int kk = 0; kk < 32; kk++) {
                uint4 u = zsP[kk * 64];
                P1BODY(u, hb, kk);
            }
        } else {
#pragma unroll
            for (int kk = 0; kk < 32; kk++) {
                uint4 u = zr_ring[kk & 7];
                zr_ring[kk & 7] = zgP[((kk + 8) & 31) * 128];
                P1BODY(u, hb, kk);
            }
        }
        az0 = bflyadd(az0); az1 = bflyadd(az1);
        ar0 = bflyadd(ar0); ar1 = bflyadd(ar1);

        const float sz = pick(row ? az1 : az0, csel);
        const float sr = pick(row ? ar1 : ar0, csel);
        zg = fast_sigm(sz + ez);
        const float rg = fast_sigm(sr + er);
        const float rh = rg * hold;
        srhdup[wc] = pk2(rh, rh);
        const float* en = g_eproj + (size_t)tok1 * 768;
        ez = __ldg(en + mycol);
        er = __ldg(en + 256 + mycol);
        __syncthreads();

        // ================= phase 2: h_tilde partials (64 k) =================
        ull ah0 = 0, ah1 = 0;
        if (smw) {
#pragma unroll
            for (int kk = 0; kk < 16; kk++) {
                uint4 u = hsP[kk * 64];
                P2BODY(u, hb, kk);
            }
        } else {
#pragma unroll
            for (int kk = 0; kk < 16; kk++) {
                uint4 u = uh_ring[kk & 3];
                uh_ring[kk & 3] = hgP[((kk + 4) & 15) * 128];
                P2BODY(u, hb, kk);
            }
        }
        ah0 = bflyadd(ah0); ah1 = bflyadd(ah1);

        const float sh = pick(row ? ah1 : ah0, csel);
        const float ht = fast_tanh(sh + eh);
        hold += zg * (ht - hold);
        hdup[wc] = pk2(hold, hold);
        eh = __ldg(en + 512 + mycol);
        {
            int s2 = (s + 2 < SSZ) ? s + 2 : SSZ - 1;
            tok1 = __ldg(&x[xrow + s2]);
        }
        __syncthreads();
    }

    g_hlast[(size_t)(b0 + row) * HSZ + mycol] = hold;
}

// ============================================================================
extern "C" void kernel_launch(void* const* d_in, const int* in_sizes, int n_in,
                              void* d_out, int out_size)
{
    const int*   x   = (const int*)  d_in[0];
    const float* emb = (const float*)d_in[1];
    const float* Wz  = (const float*)d_in[2];
    const float* bz  = (const float*)d_in[3];
    const float* Uz  = (const float*)d_in[4];
    const float* buz = (const float*)d_in[5];
    const float* Wr  = (const float*)d_in[6];
    const float* br  = (const float*)d_in[7];
    const float* Ur  = (const float*)d_in[8];
    const float* bur = (const float*)d_in[9];
    const float* Wh  = (const float*)d_in[10];
    const float* bh  = (const float*)d_in[11];
    const float* Uh  = (const float*)d_in[12];
    const float* buh = (const float*)d_in[13];
    const float* Wf  = (const float*)d_in[14];
    const float* bf  = (const float*)d_in[15];
    float* out = (float*)d_out;

    float* eproj = nullptr;
    float* hlast = nullptr;
    cudaGetSymbolAddress((void**)&eproj, g_eproj);
    cudaGetSymbolAddress((void**)&hlast, g_hlast);

    cudaFuncSetAttribute(gru_scan11,
                         cudaFuncAttributeMaxDynamicSharedMemorySize, SCAN_SM_BYTES);

    dim3 blk(256);
    pack_u<<<128, 128>>>(Uz, Ur, Uh);
    sgemm_nt_bias<<<dim3(250, 2), blk>>>(emb, Wz, bz, buz, eproj, 768, 0);
    sgemm_nt_bias<<<dim3(250, 2), blk>>>(emb, Wr, br, bur, eproj, 768, 256);
    sgemm_nt_bias<<<dim3(250, 2), blk>>>(emb, Wh, bh, buh, eproj, 768, 512);

    gru_scan11<<<128, 512, SCAN_SM_BYTES>>>(x);

    sgemm_nt_bias<<<dim3(2, 250), blk>>>(hlast, Wf, bf, nullptr, out, 32000, 0);
}

// round 12
// speedup vs baseline: 1.1390x; 1.1083x over previous
#include <cuda_runtime.h>
#include <cuda_bf16.h>

#define VSZ 32000
#define HSZ 256
#define BSZ 256
#define SSZ 512

typedef unsigned long long ull;

// Scratch (device globals; no allocation allowed)
__device__ float g_eproj[(size_t)VSZ * 768];   // emb @ [Wz;Wr;Wh]^T + biases
__device__ float g_hlast[BSZ * HSZ];
// Transposed packed bf16 U, k-grouped for uint4 loads:
//  g_zr4[k2][jg] = { z(2k2), r(2k2), z(2k2+1), r(2k2+1) }
//  g_uh4[k4][jg] = { h(4k4), h(4k4+1), h(4k4+2), h(4k4+3) }
__device__ uint4 g_zr4[128 * 128];
__device__ uint4 g_uh4[64 * 128];

// ---- packed f32x2 helpers (Blackwell sm_103a) ----
__device__ __forceinline__ ull pk2(float lo, float hi) {
    ull r;
    asm("mov.b64 %0, {%1, %2};" : "=l"(r) : "f"(lo), "f"(hi));
    return r;
}
__device__ __forceinline__ void fma2(ull& d, ull a, ull b) {
    asm("fma.rn.f32x2 %0, %1, %2, %0;" : "+l"(d) : "l"(a), "l"(b));
}
__device__ __forceinline__ ull addf2(ull a, ull b) {
    ull r;
    asm("add.rn.f32x2 %0, %1, %2;" : "=l"(r) : "l"(a), "l"(b));
    return r;
}
__device__ __forceinline__ ull bflyadd(ull v) {
    v = addf2(v, __shfl_xor_sync(0xffffffffu, v, 8));
    v = addf2(v, __shfl_xor_sync(0xffffffffu, v, 16));
    return v;
}
__device__ __forceinline__ float pick(ull v, int hi_sel) {
    float lo, hi;
    asm("mov.b64 {%0, %1}, %2;" : "=f"(lo), "=f"(hi) : "l"(v));
    return hi_sel ? hi : lo;
}
// bf16x2 (lo16, hi16) -> f32x2 pair, exact (v8-proven form)
__device__ __forceinline__ ull bf2f2(unsigned v) {
    ull r;
    asm("{\n\t.reg .b32 lo, hi;\n\t"
        "shl.b32 lo, %1, 16;\n\t"
        "and.b32 hi, %1, 0xFFFF0000;\n\t"
        "mov.b64 %0, {lo, hi};\n\t}" : "=l"(r) : "r"(v));
    return r;
}
__device__ __forceinline__ float fast_sigm(float x) {
    float e, r;
    asm("ex2.approx.ftz.f32 %0, %1;" : "=f"(e) : "f"(-1.4426950408889634f * x));
    asm("rcp.approx.ftz.f32 %0, %1;" : "=f"(r) : "f"(1.0f + e));
    return r;
}
__device__ __forceinline__ float fast_tanh(float x) {
    float r;
    asm("tanh.approx.f32 %0, %1;" : "=f"(r) : "f"(x));
    return r;
}
__device__ __forceinline__ unsigned pkbf(float lo, float hi) {
    unsigned short l = __bfloat16_as_ushort(__float2bfloat16(lo));
    unsigned short h = __bfloat16_as_ushort(__float2bfloat16(hi));
    return ((unsigned)h << 16) | (unsigned)l;
}

// ============================================================================
// Pack U into transposed bf16 uint4 streams
// ============================================================================
__global__ void pack_u(const float* __restrict__ Uz, const float* __restrict__ Ur,
                       const float* __restrict__ Uh)
{
    const int k2 = blockIdx.x;     // 0..127
    const int jg = threadIdx.x;    // 0..127
    const int j0 = 2 * jg;
    const int ka = 2 * k2, kb = 2 * k2 + 1;
    uint4 v;
    v.x = pkbf(Uz[j0 * 256 + ka], Uz[(j0 + 1) * 256 + ka]);
    v.y = pkbf(Ur[j0 * 256 + ka], Ur[(j0 + 1) * 256 + ka]);
    v.z = pkbf(Uz[j0 * 256 + kb], Uz[(j0 + 1) * 256 + kb]);
    v.w = pkbf(Ur[j0 * 256 + kb], Ur[(j0 + 1) * 256 + kb]);
    g_zr4[k2 * 128 + jg] = v;
    if (k2 < 64) {
        const int kc = 4 * k2;
        uint4 h;
        h.x = pkbf(Uh[j0 * 256 + kc],     Uh[(j0 + 1) * 256 + kc]);
        h.y = pkbf(Uh[j0 * 256 + kc + 1], Uh[(j0 + 1) * 256 + kc + 1]);
        h.z = pkbf(Uh[j0 * 256 + kc + 2], Uh[(j0 + 1) * 256 + kc + 2]);
        h.w = pkbf(Uh[j0 * 256 + kc + 3], Uh[(j0 + 1) * 256 + kc + 3]);
        g_uh4[k2 * 128 + jg] = h;
    }
}

// Trivial shim launch: shifts gru_scan to ncu's -s 5 capture slot.
__global__ void init_hlast_kernel()
{
    g_hlast[blockIdx.x * 256 + threadIdx.x] = 0.0f;
}

// ============================================================================
// SGEMM-NT with bias (~90% of scalar f32x2 floor)
// ============================================================================
__global__ void __launch_bounds__(256) sgemm_nt_bias(
    const float* __restrict__ A, const float* __restrict__ Bw,
    const float* __restrict__ bias1, const float* __restrict__ bias2,
    float* __restrict__ C, int ldc, int coloff)
{
    __shared__ __align__(16) float As[16][132];
    __shared__ __align__(16) float Bs[16][132];
    const int t  = threadIdx.x;
    const int tm = t >> 4;
    const int tn = t & 15;

    ull acc[8][4];
#pragma unroll
    for (int i = 0; i < 8; i++)
#pragma unroll
        for (int j = 0; j < 4; j++) acc[i][j] = 0ULL;

    const float* Ab = A  + (size_t)blockIdx.x * 128 * 256;
    const float* Bb = Bw + (size_t)blockIdx.y * 128 * 256;
    const int lr = t >> 2;
    const int lk = (t & 3) << 2;

    for (int k0 = 0; k0 < 256; k0 += 16) {
        float4 a0 = *(const float4*)(Ab + (size_t)lr * 256 + k0 + lk);
        float4 a1 = *(const float4*)(Ab + (size_t)(lr + 64) * 256 + k0 + lk);
        float4 b0 = *(const float4*)(Bb + (size_t)lr * 256 + k0 + lk);
        float4 b1 = *(const float4*)(Bb + (size_t)(lr + 64) * 256 + k0 + lk);
        __syncthreads();
        As[lk + 0][lr] = a0.x; As[lk + 1][lr] = a0.y;
        As[lk + 2][lr] = a0.z; As[lk + 3][lr] = a0.w;
        As[lk + 0][lr + 64] = a1.x; As[lk + 1][lr + 64] = a1.y;
        As[lk + 2][lr + 64] = a1.z; As[lk + 3][lr + 64] = a1.w;
        Bs[lk + 0][lr] = b0.x; Bs[lk + 1][lr] = b0.y;
        Bs[lk + 2][lr] = b0.z; Bs[lk + 3][lr] = b0.w;
        Bs[lk + 0][lr + 64] = b1.x; Bs[lk + 1][lr + 64] = b1.y;
        Bs[lk + 2][lr + 64] = b1.z; Bs[lk + 3][lr + 64] = b1.w;
        __syncthreads();
#pragma unroll
        for (int kk = 0; kk < 16; kk++) {
            float4 av0 = *(const float4*)(&As[kk][tm * 8]);
            float4 av1 = *(const float4*)(&As[kk][tm * 8 + 4]);
            const ull* bp = (const ull*)(&Bs[kk][tn * 8]);
            ull b2_0 = bp[0], b2_1 = bp[1], b2_2 = bp[2], b2_3 = bp[3];
            float av[8] = {av0.x, av0.y, av0.z, av0.w, av1.x, av1.y, av1.z, av1.w};
#pragma unroll
            for (int i = 0; i < 8; i++) {
                ull a2 = pk2(av[i], av[i]);
                fma2(acc[i][0], a2, b2_0);
                fma2(acc[i][1], a2, b2_1);
                fma2(acc[i][2], a2, b2_2);
                fma2(acc[i][3], a2, b2_3);
            }
        }
    }

    const int row0 = blockIdx.x * 128 + tm * 8;
    const int col0 = blockIdx.y * 128 + tn * 8;
#pragma unroll
    for (int i = 0; i < 8; i++) {
#pragma unroll
        for (int j = 0; j < 4; j++) {
            float lo, hi;
            asm("mov.b64 {%0, %1}, %2;" : "=f"(lo), "=f"(hi) : "l"(acc[i][j]));
            int n0 = col0 + j * 2;
            float e0 = bias1[n0]     + (bias2 ? bias2[n0]     : 0.0f);
            float e1 = bias1[n0 + 1] + (bias2 ? bias2[n0 + 1] : 0.0f);
            C[(size_t)(row0 + i) * ldc + coloff + n0]     = lo + e0;
            C[(size_t)(row0 + i) * ldc + coloff + n0 + 1] = hi + e1;
        }
    }
}

// ============================================================================
// GRU scan v12: EXACT v8 structure and inner loop (column-pinned jg<64,
// warp-butterfly, SHL+AND expansion). Only delta: phase-2 global ring
// deepened 4 -> 8 (cross-step alignment verified for refill mask (kk+8)&15).
// ============================================================================
#define SCAN_SM_BYTES 204928

#define P1BODY(u, hb, kk)                                                   \
    {                                                                       \
        ull uz0 = bf2f2((u).x), ur0 = bf2f2((u).y);                         \
        ull uz1 = bf2f2((u).z), ur1 = bf2f2((u).w);                         \
        ulonglong2 h0 = *(const ulonglong2*)(hdup + (hb) + 4 * (kk));       \
        ulonglong2 h1 = *(const ulonglong2*)(hdup + (hb) + 4 * (kk) + 2);   \
        fma2(az0, uz0, h0.x); fma2(az1, uz0, h0.y);                         \
        fma2(ar0, ur0, h0.x); fma2(ar1, ur0, h0.y);                         \
        fma2(az0, uz1, h1.x); fma2(az1, uz1, h1.y);                         \
        fma2(ar0, ur1, h1.x); fma2(ar1, ur1, h1.y);                         \
    }

#define P2BODY(u, sb, kk)                                                   \
    {                                                                       \
        ull uh0 = bf2f2((u).x), uh1 = bf2f2((u).y);                         \
        ull uh2 = bf2f2((u).z), uh3 = bf2f2((u).w);                         \
        ulonglong2 s0 = *(const ulonglong2*)(srhdup + (sb) + 8 * (kk));     \
        ulonglong2 s1 = *(const ulonglong2*)(srhdup + (sb) + 8 * (kk) + 2); \
        ulonglong2 s2 = *(const ulonglong2*)(srhdup + (sb) + 8 * (kk) + 4); \
        ulonglong2 s3 = *(const ulonglong2*)(srhdup + (sb) + 8 * (kk) + 6); \
        fma2(ah0, uh0, s0.x); fma2(ah1, uh0, s0.y);                         \
        fma2(ah0, uh1, s1.x); fma2(ah1, uh1, s1.y);                         \
        fma2(ah0, uh2, s2.x); fma2(ah1, uh2, s2.y);                         \
        fma2(ah0, uh3, s3.x); fma2(ah1, uh3, s3.y);                         \
    }

__global__ void __launch_bounds__(512, 1) gru_scan12(const int* __restrict__ x)
{
    extern __shared__ __align__(16) char smraw[];
    uint4* pin_zr4 = (uint4*)smraw;                   // [k2<128][jg<64] 131072 B
    uint4* pin_uh4 = (uint4*)(smraw + 131072);        // [k4<64][jg<64]   65536 B
    ull*   hdup    = (ull*)(smraw + 196608);          // 520 ull, padded
    ull*   srhdup  = (ull*)(smraw + 200768);          // 520 ull, padded

    const int t    = threadIdx.x;
    const int lane = t & 31;
    const int w    = t >> 5;
    const int jp   = (w << 3) | (lane & 7);   // col-pair 0..127
    const int kh   = lane >> 3;               // 0..3
    const int row  = kh & 1;
    const int csel = kh >> 1;
    const int mycol = (jp << 1) | csel;
    const int b0   = blockIdx.x * 2;
    const bool smw = (w < 8);                 // uniform per warp

    // ---- pin columns jg<64 + zero padded state ----
    for (int i = t; i < 128 * 64; i += 512)
        pin_zr4[i] = g_zr4[(i >> 6) * 128 + (i & 63)];
    for (int i = t; i < 64 * 64; i += 512)
        pin_uh4[i] = g_uh4[(i >> 6) * 128 + (i & 63)];
    for (int i = t; i < 520; i += 512) { hdup[i] = 0ULL; srhdup[i] = 0ULL; }
    __syncthreads();

    // per-warp-uniform stream bases (k2 base = kh*32; k4 base = kh*16)
    const uint4* zsP = pin_zr4 + (kh * 32) * 64 + jp;        // smem, stride 64
    const uint4* zgP = g_zr4   + (kh * 32) * 128 + jp;       // gmem, stride 128
    const uint4* hsP = pin_uh4 + (kh * 16) * 64 + jp;
    const uint4* hgP = g_uh4   + (kh * 16) * 128 + jp;
    const int hb = 130 * kh;   // padded ull base for this kh's 64-k block

    // global register rings (only live for global warps).
    // zr: depth 8 over 32 iters, slot kk&7, refill (kk+8)&31  (v8-proven)
    // uh: depth 8 over 16 iters, slot kk&7, refill (kk+8)&15  (verified aligned)
    uint4 zr_ring[8], uh_ring[8];
    if (!smw) {
#pragma unroll
        for (int i = 0; i < 8; i++) zr_ring[i] = zgP[i * 128];
#pragma unroll
        for (int i = 0; i < 8; i++) uh_ring[i] = hgP[i * 128];
    }

    // lane-owned state + e/token pipeline
    float hold = 0.0f, zg = 0.0f;
    const int xrow = (b0 + row) * SSZ;
    const int wc = 2 * mycol + row + ((mycol >> 6) << 1);   // padded state idx
    int tok = __ldg(&x[xrow]);
    const float* e0 = g_eproj + (size_t)tok * 768;
    float ez = __ldg(e0 + mycol);
    float er = __ldg(e0 + 256 + mycol);
    float eh = __ldg(e0 + 512 + mycol);
    int tok1 = __ldg(&x[xrow + 1]);

    for (int s = 0; s < SSZ; s++) {
        // ================= phase 1: z, r partials (64 k) =================
        ull az0 = 0, az1 = 0, ar0 = 0, ar1 = 0;
        if (smw) {
#pragma unroll
            for (int kk = 0; kk < 32; kk++) {
                uint4 u = zsP[kk * 64];
                P1BODY(u, hb, kk);
            }
        } else {
#pragma unroll
            for (int kk = 0; kk < 32; kk++) {
                uint4 u = zr_ring[kk & 7];
                zr_ring[kk & 7] = zgP[((kk + 8) & 31) * 128];
                P1BODY(u, hb, kk);
            }
        }
        az0 = bflyadd(az0); az1 = bflyadd(az1);
        ar0 = bflyadd(ar0); ar1 = bflyadd(ar1);

        const float sz = pick(row ? az1 : az0, csel);
        const float sr = pick(row ? ar1 : ar0, csel);
        zg = fast_sigm(sz + ez);
        const float rg = fast_sigm(sr + er);
        const float rh = rg * hold;
        srhdup[wc] = pk2(rh, rh);
        const float* en = g_eproj + (size_t)tok1 * 768;
        ez = __ldg(en + mycol);
        er = __ldg(en + 256 + mycol);
        __syncthreads();

        // ================= phase 2: h_tilde partials (64 k) =================
        ull ah0 = 0, ah1 = 0;
        if (smw) {
#pragma unroll
            for (int kk = 0; kk < 16; kk++) {
                uint4 u = hsP[kk * 64];
                P2BODY(u, hb, kk);
            }
        } else {
#pragma unroll
            for (int kk = 0; kk < 16; kk++) {
                uint4 u = uh_ring[kk & 7];
                uh_ring[kk & 7] = hgP[((kk + 8) & 15) * 128];
                P2BODY(u, hb, kk);
            }
        }
        ah0 = bflyadd(ah0); ah1 = bflyadd(ah1);

        const float sh = pick(row ? ah1 : ah0, csel);
        const float ht = fast_tanh(sh + eh);
        hold += zg * (ht - hold);
        hdup[wc] = pk2(hold, hold);
        eh = __ldg(en + 512 + mycol);
        {
            int s2 = (s + 2 < SSZ) ? s + 2 : SSZ - 1;
            tok1 = __ldg(&x[xrow + s2]);
        }
        __syncthreads();
    }

    g_hlast[(size_t)(b0 + row) * HSZ + mycol] = hold;
}

// ============================================================================
extern "C" void kernel_launch(void* const* d_in, const int* in_sizes, int n_in,
                              void* d_out, int out_size)
{
    const int*   x   = (const int*)  d_in[0];
    const float* emb = (const float*)d_in[1];
    const float* Wz  = (const float*)d_in[2];
    const float* bz  = (const float*)d_in[3];
    const float* Uz  = (const float*)d_in[4];
    const float* buz = (const float*)d_in[5];
    const float* Wr  = (const float*)d_in[6];
    const float* br  = (const float*)d_in[7];
    const float* Ur  = (const float*)d_in[8];
    const float* bur = (const float*)d_in[9];
    const float* Wh  = (const float*)d_in[10];
    const float* bh  = (const float*)d_in[11];
    const float* Uh  = (const float*)d_in[12];
    const float* buh = (const float*)d_in[13];
    const float* Wf  = (const float*)d_in[14];
    const float* bf  = (const float*)d_in[15];
    float* out = (float*)d_out;

    float* eproj = nullptr;
    float* hlast = nullptr;
    cudaGetSymbolAddress((void**)&eproj, g_eproj);
    cudaGetSymbolAddress((void**)&hlast, g_hlast);

    cudaFuncSetAttribute(gru_scan12,
                         cudaFuncAttributeMaxDynamicSharedMemorySize, SCAN_SM_BYTES);

    dim3 blk(256);
    pack_u<<<128, 128>>>(Uz, Ur, Uh);                                      // 0
    sgemm_nt_bias<<<dim3(250, 2), blk>>>(emb, Wz, bz, buz, eproj, 768, 0);   // 1
    sgemm_nt_bias<<<dim3(250, 2), blk>>>(emb, Wr, br, bur, eproj, 768, 256); // 2
    sgemm_nt_bias<<<dim3(250, 2), blk>>>(emb, Wh, bh, buh, eproj, 768, 512); // 3
    init_hlast_kernel<<<256, 256>>>();                                     // 4 (shim)
    gru_scan12<<<128, 512, SCAN_SM_BYTES>>>(x);                            // 5 <- ncu
    sgemm_nt_bias<<<dim3(2, 250), blk>>>(hlast, Wf, bf, nullptr, out, 32000, 0); // 6
}

// round 16
// speedup vs baseline: 1.2403x; 1.0889x over previous
#include <cuda_runtime.h>
#include <cuda_bf16.h>
#include <cstdint>

#define VSZ 32000
#define HSZ 256
#define BSZ 256
#define SSZ 512

typedef unsigned long long ull;

// ---------------- device globals (no allocation allowed) ----------------
__device__ float g_eproj[(size_t)VSZ * 768];   // emb @ [Wz;Wr;Wh]^T + biases
__device__ float g_hlast[BSZ * HSZ];
// bf16 U streams for the scan (v8 layout)
__device__ uint4 g_zr4[128 * 128];
__device__ uint4 g_uh4[64 * 128];
// split-precision operands for the HMMA eproj GEMM (hi = bf16(x), lo = bf16(x-hi))
__device__ __nv_bfloat16 g_emb_hi[(size_t)VSZ * 256];
__device__ __nv_bfloat16 g_emb_lo[(size_t)VSZ * 256];
__device__ __nv_bfloat16 g_w_hi[768 * 256];
__device__ __nv_bfloat16 g_w_lo[768 * 256];
__device__ float g_bias768[768];

// ---------------- packed f32x2 helpers ----------------
__device__ __forceinline__ ull pk2(float lo, float hi) {
    ull r;
    asm("mov.b64 %0, {%1, %2};" : "=l"(r) : "f"(lo), "f"(hi));
    return r;
}
__device__ __forceinline__ void fma2(ull& d, ull a, ull b) {
    asm("fma.rn.f32x2 %0, %1, %2, %0;" : "+l"(d) : "l"(a), "l"(b));
}
__device__ __forceinline__ ull addf2(ull a, ull b) {
    ull r;
    asm("add.rn.f32x2 %0, %1, %2;" : "=l"(r) : "l"(a), "l"(b));
    return r;
}
__device__ __forceinline__ ull bflyadd(ull v) {
    v = addf2(v, __shfl_xor_sync(0xffffffffu, v, 8));
    v = addf2(v, __shfl_xor_sync(0xffffffffu, v, 16));
    return v;
}
__device__ __forceinline__ float pick(ull v, int hi_sel) {
    float lo, hi;
    asm("mov.b64 {%0, %1}, %2;" : "=f"(lo), "=f"(hi) : "l"(v));
    return hi_sel ? hi : lo;
}
__device__ __forceinline__ ull bf2f2(unsigned v) {
    ull r;
    asm("{\n\t.reg .b32 lo, hi;\n\t"
        "shl.b32 lo, %1, 16;\n\t"
        "and.b32 hi, %1, 0xFFFF0000;\n\t"
        "mov.b64 %0, {lo, hi};\n\t}" : "=l"(r) : "r"(v));
    return r;
}
__device__ __forceinline__ float fast_sigm(float x) {
    float e, r;
    asm("ex2.approx.ftz.f32 %0, %1;" : "=f"(e) : "f"(-1.4426950408889634f * x));
    asm("rcp.approx.ftz.f32 %0, %1;" : "=f"(r) : "f"(1.0f + e));
    return r;
}
__device__ __forceinline__ float fast_tanh(float x) {
    float r;
    asm("tanh.approx.f32 %0, %1;" : "=f"(r) : "f"(x));
    return r;
}
__device__ __forceinline__ unsigned pkbf(float lo, float hi) {
    unsigned short l = __bfloat16_as_ushort(__float2bfloat16(lo));
    unsigned short h = __bfloat16_as_ushort(__float2bfloat16(hi));
    return ((unsigned)h << 16) | (unsigned)l;
}
__device__ __forceinline__ uint32_t s2u(const void* p) {
    uint32_t a;
    asm("{ .reg .u64 t; cvta.to.shared.u64 t, %1; cvt.u32.u64 %0, t; }"
        : "=r"(a) : "l"(p));
    return a;
}
__device__ __forceinline__ void ldsm4(uint32_t& r0, uint32_t& r1,
                                      uint32_t& r2, uint32_t& r3, uint32_t addr) {
    asm volatile("ldmatrix.sync.aligned.m8n8.x4.shared.b16 {%0,%1,%2,%3}, [%4];"
                 : "=r"(r0), "=r"(r1), "=r"(r2), "=r"(r3) : "r"(addr));
}
__device__ __forceinline__ void mma16816(float* d, const uint32_t* a,
                                         const uint32_t* b) {
    asm volatile(
        "mma.sync.aligned.m16n8k16.row.col.f32.bf16.bf16.f32 "
        "{%0,%1,%2,%3}, {%4,%5,%6,%7}, {%8,%9}, {%0,%1,%2,%3};"
        : "+f"(d[0]), "+f"(d[1]), "+f"(d[2]), "+f"(d[3])
        : "r"(a[0]), "r"(a[1]), "r"(a[2]), "r"(a[3]), "r"(b[0]), "r"(b[1]));
}

// ============================================================================
// Pack U into transposed bf16 uint4 streams (scan operands)
// ============================================================================
__global__ void pack_u(const float* __restrict__ Uz, const float* __restrict__ Ur,
                       const float* __restrict__ Uh)
{
    const int k2 = blockIdx.x;
    const int jg = threadIdx.x;
    const int j0 = 2 * jg;
    const int ka = 2 * k2, kb = 2 * k2 + 1;
    uint4 v;
    v.x = pkbf(Uz[j0 * 256 + ka], Uz[(j0 + 1) * 256 + ka]);
    v.y = pkbf(Ur[j0 * 256 + ka], Ur[(j0 + 1) * 256 + ka]);
    v.z = pkbf(Uz[j0 * 256 + kb], Uz[(j0 + 1) * 256 + kb]);
    v.w = pkbf(Ur[j0 * 256 + kb], Ur[(j0 + 1) * 256 + kb]);
    g_zr4[k2 * 128 + jg] = v;
    if (k2 < 64) {
        const int kc = 4 * k2;
        uint4 h;
        h.x = pkbf(Uh[j0 * 256 + kc],     Uh[(j0 + 1) * 256 + kc]);
        h.y = pkbf(Uh[j0 * 256 + kc + 1], Uh[(j0 + 1) * 256 + kc + 1]);
        h.z = pkbf(Uh[j0 * 256 + kc + 2], Uh[(j0 + 1) * 256 + kc + 2]);
        h.w = pkbf(Uh[j0 * 256 + kc + 3], Uh[(j0 + 1) * 256 + kc + 3]);
        g_uh4[k2 * 128 + jg] = h;
    }
}

// ============================================================================
// fp32 -> split bf16 hi/lo (emb + [Wz;Wr;Wh]) + bias pre-sum
// ============================================================================
__global__ void cvt_split(const float* __restrict__ emb,
                          const float* __restrict__ Wz, const float* __restrict__ Wr,
                          const float* __restrict__ Wh,
                          const float* __restrict__ bz, const float* __restrict__ buz,
                          const float* __restrict__ br, const float* __restrict__ bur,
                          const float* __restrict__ bh, const float* __restrict__ buh)
{
    const size_t idx = (size_t)blockIdx.x * 1024 + threadIdx.x;
    if (blockIdx.y == 0) {
        float v = emb[idx];
        __nv_bfloat16 h = __float2bfloat16(v);
        g_emb_hi[idx] = h;
        g_emb_lo[idx] = __float2bfloat16(v - __bfloat162float(h));
    } else {
        if (idx < 196608) {
            float v = (idx < 65536) ? Wz[idx]
                    : (idx < 131072) ? Wr[idx - 65536]
                                     : Wh[idx - 131072];
            __nv_bfloat16 h = __float2bfloat16(v);
            g_w_hi[idx] = h;
            g_w_lo[idx] = __float2bfloat16(v - __bfloat162float(h));
        }
        if (idx < 768) {
            int g = (int)(idx >> 8), j = (int)(idx & 255);
            g_bias768[idx] = (g == 0) ? bz[j] + buz[j]
                           : (g == 1) ? br[j] + bur[j]
                                      : bh[j] + buh[j];
        }
    }
}

__global__ void shim_zero()
{
    g_hlast[blockIdx.x * 256 + threadIdx.x] = 0.0f;
}

// ============================================================================
// Split-precision HMMA GEMM (NT): D = (Ah+Al) @ (Bh+Bl)^T + bias, computed as
// Ah.Bh + Ah.Bl + Al.Bh (Al.Bl ~2^-18, dropped) -> effectively fp32 accurate.
// 128x128 tile, K=256 in two 128-k passes; 4 sub-tiles staged per pass.
// 256 thr, 8 warps (4x2), warp tile 32x64. Row stride 136 bf16 (272B: 16B
// phase shift per row -> conflict-free ldmatrix).
// ============================================================================
#define GS2 136
#define GEMM_SMEM (4 * 128 * GS2 * 2)   // 139264 B

__global__ void __launch_bounds__(256) gemm_mma3(
    const __nv_bfloat16* __restrict__ Ah, const __nv_bfloat16* __restrict__ Al,
    const __nv_bfloat16* __restrict__ Bh, const __nv_bfloat16* __restrict__ Bl,
    const float* __restrict__ bias, float* __restrict__ C, int ldc)
{
    extern __shared__ __align__(16) char sm[];
    __nv_bfloat16* sAh = (__nv_bfloat16*)sm;
    __nv_bfloat16* sAl = sAh + 128 * GS2;
    __nv_bfloat16* sBh = sAl + 128 * GS2;
    __nv_bfloat16* sBl = sBh + 128 * GS2;

    const int t = threadIdx.x, w = t >> 5, lane = t & 31;
    const int wm = w & 3, wn = w >> 2;
    const int r = lane & 7, sel = lane >> 3;

    // per-lane relative ldmatrix offsets (bytes within a tile)
    uint32_t aRel[2], bRel[4];
#pragma unroll
    for (int mi = 0; mi < 2; mi++) {
        int row = wm * 32 + mi * 16 + (sel & 1) * 8 + r;
        aRel[mi] = (uint32_t)(row * GS2 + (sel >> 1) * 8) * 2;
    }
#pragma unroll
    for (int nq = 0; nq < 4; nq++) {
        int row = wn * 64 + nq * 16 + (sel >> 1) * 8 + r;
        bRel[nq] = (uint32_t)(row * GS2 + (sel & 1) * 8) * 2;
    }
    const uint32_t sah = s2u(sAh), sal = s2u(sAl);
    const uint32_t sbh = s2u(sBh), sbl = s2u(sBl);

    float acc[2][8][4];
#pragma unroll
    for (int mi = 0; mi < 2; mi++)
#pragma unroll
        for (int ni = 0; ni < 8; ni++)
#pragma unroll
            for (int c = 0; c < 4; c++) acc[mi][ni][c] = 0.0f;

    const size_t aBase = (size_t)blockIdx.x * 128 * 256;
    const size_t bBase = (size_t)blockIdx.y * 128 * 256;

    for (int kc = 0; kc < 2; kc++) {
        if (kc) __syncthreads();           // protect previous pass reads
        // stage 4 sub-tiles [128 rows x 128 k]
        const uint4* Ahg = (const uint4*)(Ah + aBase) + kc * 16;
        const uint4* Alg = (const uint4*)(Al + aBase) + kc * 16;
        const uint4* Bhg = (const uint4*)(Bh + bBase) + kc * 16;
        const uint4* Blg = (const uint4*)(Bl + bBase) + kc * 16;
        for (int i = t; i < 2048; i += 256) {
            int row = i >> 4, q = i & 15;       // q: uint4 within 128-k row
            size_t g = (size_t)row * 32 + q;    // full row = 32 uint4
            uint32_t so = (uint32_t)(row * GS2 + q * 8);
            *(uint4*)(sAh + so) = Ahg[g];
            *(uint4*)(sAl + so) = Alg[g];
            *(uint4*)(sBh + so) = Bhg[g];
            *(uint4*)(sBl + so) = Blg[g];
        }
        __syncthreads();

#pragma unroll
        for (int ks = 0; ks < 8; ks++) {
            const uint32_t kb = (uint32_t)(ks * 32);
            uint32_t afh[2][4], afl[2][4], bfh[8][2], bfl[8][2];
#pragma unroll
            for (int mi = 0; mi < 2; mi++) {
                ldsm4(afh[mi][0], afh[mi][1], afh[mi][2], afh[mi][3],
                      sah + aRel[mi] + kb);
                ldsm4(afl[mi][0], afl[mi][1], afl[mi][2], afl[mi][3],
                      sal + aRel[mi] + kb);
            }
#pragma unroll
            for (int nq = 0; nq < 4; nq++) {
                uint32_t b0, b1, b2, b3;
                ldsm4(b0, b1, b2, b3, sbh + bRel[nq] + kb);
                bfh[2 * nq][0] = b0;     bfh[2 * nq][1] = b1;
                bfh[2 * nq + 1][0] = b2; bfh[2 * nq + 1][1] = b3;
                ldsm4(b0, b1, b2, b3, sbl + bRel[nq] + kb);
                bfl[2 * nq][0] = b0;     bfl[2 * nq][1] = b1;
                bfl[2 * nq + 1][0] = b2; bfl[2 * nq + 1][1] = b3;
            }
#pragma unroll
            for (int mi = 0; mi < 2; mi++)
#pragma unroll
                for (int ni = 0; ni < 8; ni++) {
                    mma16816(acc[mi][ni], afh[mi], bfh[ni]);
                    mma16816(acc[mi][ni], afh[mi], bfl[ni]);
                    mma16816(acc[mi][ni], afl[mi], bfh[ni]);
                }
        }
    }

    const int co = blockIdx.y * 128;
    const int rbase = blockIdx.x * 128 + wm * 32 + (lane >> 2);
    const int cb = wn * 64 + (lane & 3) * 2;
#pragma unroll
    for (int mi = 0; mi < 2; mi++) {
#pragma unroll
        for (int half = 0; half < 2; half++) {
            const int grow = rbase + mi * 16 + half * 8;
            float* cp = C + (size_t)grow * ldc + co;
#pragma unroll
            for (int ni = 0; ni < 8; ni++) {
                const int col = cb + ni * 8;
                float2 v;
                v.x = acc[mi][ni][half * 2]     + bias[co + col];
                v.y = acc[mi][ni][half * 2 + 1] + bias[co + col + 1];
                *(float2*)(cp + col) = v;
            }
        }
    }
}

// ============================================================================
// Exact fp32 scalar SGEMM-NT with bias (logits — precision-critical)
// ============================================================================
__global__ void __launch_bounds__(256) sgemm_nt_bias(
    const float* __restrict__ A, const float* __restrict__ Bw,
    const float* __restrict__ bias1, float* __restrict__ C, int ldc)
{
    __shared__ __align__(16) float As[16][132];
    __shared__ __align__(16) float Bs[16][132];
    const int t  = threadIdx.x;
    const int tm = t >> 4;
    const int tn = t & 15;

    ull acc[8][4];
#pragma unroll
    for (int i = 0; i < 8; i++)
#pragma unroll
        for (int j = 0; j < 4; j++) acc[i][j] = 0ULL;

    const float* Ab = A  + (size_t)blockIdx.x * 128 * 256;
    const float* Bb = Bw + (size_t)blockIdx.y * 128 * 256;
    const int lr = t >> 2;
    const int lk = (t & 3) << 2;

    for (int k0 = 0; k0 < 256; k0 += 16) {
        float4 a0 = *(const float4*)(Ab + (size_t)lr * 256 + k0 + lk);
        float4 a1 = *(const float4*)(Ab + (size_t)(lr + 64) * 256 + k0 + lk);
        float4 b0 = *(const float4*)(Bb + (size_t)lr * 256 + k0 + lk);
        float4 b1 = *(const float4*)(Bb + (size_t)(lr + 64) * 256 + k0 + lk);
        __syncthreads();
        As[lk + 0][lr] = a0.x; As[lk + 1][lr] = a0.y;
        As[lk + 2][lr] = a0.z; As[lk + 3][lr] = a0.w;
        As[lk + 0][lr + 64] = a1.x; As[lk + 1][lr + 64] = a1.y;
        As[lk + 2][lr + 64] = a1.z; As[lk + 3][lr + 64] = a1.w;
        Bs[lk + 0][lr] = b0.x; Bs[lk + 1][lr] = b0.y;
        Bs[lk + 2][lr] = b0.z; Bs[lk + 3][lr] = b0.w;
        Bs[lk + 0][lr + 64] = b1.x; Bs[lk + 1][lr + 64] = b1.y;
        Bs[lk + 2][lr + 64] = b1.z; Bs[lk + 3][lr + 64] = b1.w;
        __syncthreads();
#pragma unroll
        for (int kk = 0; kk < 16; kk++) {
            float4 av0 = *(const float4*)(&As[kk][tm * 8]);
            float4 av1 = *(const float4*)(&As[kk][tm * 8 + 4]);
            const ull* bp = (const ull*)(&Bs[kk][tn * 8]);
            ull b2_0 = bp[0], b2_1 = bp[1], b2_2 = bp[2], b2_3 = bp[3];
            float av[8] = {av0.x, av0.y, av0.z, av0.w, av1.x, av1.y, av1.z, av1.w};
#pragma unroll
            for (int i = 0; i < 8; i++) {
                ull a2 = pk2(av[i], av[i]);
                fma2(acc[i][0], a2, b2_0);
                fma2(acc[i][1], a2, b2_1);
                fma2(acc[i][2], a2, b2_2);
                fma2(acc[i][3], a2, b2_3);
            }
        }
    }

    const int row0 = blockIdx.x * 128 + tm * 8;
    const int col0 = blockIdx.y * 128 + tn * 8;
#pragma unroll
    for (int i = 0; i < 8; i++) {
#pragma unroll
        for (int j = 0; j < 4; j++) {
            float lo, hi;
            asm("mov.b64 {%0, %1}, %2;" : "=f"(lo), "=f"(hi) : "l"(acc[i][j]));
            int n0 = col0 + j * 2;
            C[(size_t)(row0 + i) * ldc + n0]     = lo + bias1[n0];
            C[(size_t)(row0 + i) * ldc + n0 + 1] = hi + bias1[n0 + 1];
        }
    }
}

// ============================================================================
// GRU scan: EXACT v8 (2706us). Untouched.
// ============================================================================
#define SCAN_SM_BYTES 204928

#define P1BODY(u, hb, kk)                                                   \
    {                                                                       \
        ull uz0 = bf2f2((u).x), ur0 = bf2f2((u).y);                         \
        ull uz1 = bf2f2((u).z), ur1 = bf2f2((u).w);                         \
        ulonglong2 h0 = *(const ulonglong2*)(hdup + (hb) + 4 * (kk));       \
        ulonglong2 h1 = *(const ulonglong2*)(hdup + (hb) + 4 * (kk) + 2);   \
        fma2(az0, uz0, h0.x); fma2(az1, uz0, h0.y);                         \
        fma2(ar0, ur0, h0.x); fma2(ar1, ur0, h0.y);                         \
        fma2(az0, uz1, h1.x); fma2(az1, uz1, h1.y);                         \
        fma2(ar0, ur1, h1.x); fma2(ar1, ur1, h1.y);                         \
    }

#define P2BODY(u, sb, kk)                                                   \
    {                                                                       \
        ull uh0 = bf2f2((u).x), uh1 = bf2f2((u).y);                         \
        ull uh2 = bf2f2((u).z), uh3 = bf2f2((u).w);                         \
        ulonglong2 s0 = *(const ulonglong2*)(srhdup + (sb) + 8 * (kk));     \
        ulonglong2 s1 = *(const ulonglong2*)(srhdup + (sb) + 8 * (kk) + 2); \
        ulonglong2 s2 = *(const ulonglong2*)(srhdup + (sb) + 8 * (kk) + 4); \
        ulonglong2 s3 = *(const ulonglong2*)(srhdup + (sb) + 8 * (kk) + 6); \
        fma2(ah0, uh0, s0.x); fma2(ah1, uh0, s0.y);                         \
        fma2(ah0, uh1, s1.x); fma2(ah1, uh1, s1.y);                         \
        fma2(ah0, uh2, s2.x); fma2(ah1, uh2, s2.y);                         \
        fma2(ah0, uh3, s3.x); fma2(ah1, uh3, s3.y);                         \
    }

__global__ void __launch_bounds__(512, 1) gru_scan16(const int* __restrict__ x)
{
    extern __shared__ __align__(16) char smraw[];
    uint4* pin_zr4 = (uint4*)smraw;
    uint4* pin_uh4 = (uint4*)(smraw + 131072);
    ull*   hdup    = (ull*)(smraw + 196608);
    ull*   srhdup  = (ull*)(smraw + 200768);

    const int t    = threadIdx.x;
    const int lane = t & 31;
    const int w    = t >> 5;
    const int jp   = (w << 3) | (lane & 7);
    const int kh   = lane >> 3;
    const int row  = kh & 1;
    const int csel = kh >> 1;
    const int mycol = (jp << 1) | csel;
    const int b0   = blockIdx.x * 2;
    const bool smw = (w < 8);

    for (int i = t; i < 128 * 64; i += 512)
        pin_zr4[i] = g_zr4[(i >> 6) * 128 + (i & 63)];
    for (int i = t; i < 64 * 64; i += 512)
        pin_uh4[i] = g_uh4[(i >> 6) * 128 + (i & 63)];
    for (int i = t; i < 520; i += 512) { hdup[i] = 0ULL; srhdup[i] = 0ULL; }
    __syncthreads();

    const uint4* zsP = pin_zr4 + (kh * 32) * 64 + jp;
    const uint4* zgP = g_zr4   + (kh * 32) * 128 + jp;
    const uint4* hsP = pin_uh4 + (kh * 16) * 64 + jp;
    const uint4* hgP = g_uh4   + (kh * 16) * 128 + jp;
    const int hb = 130 * kh;

    uint4 zr_ring[8], uh_ring[4];
    if (!smw) {
#pragma unroll
        for (int i = 0; i < 8; i++) zr_ring[i] = zgP[i * 128];
#pragma unroll
        for (int i = 0; i < 4; i++) uh_ring[i] = hgP[i * 128];
    }

    float hold = 0.0f, zg = 0.0f;
    const int xrow = (b0 + row) * SSZ;
    const int wc = 2 * mycol + row + ((mycol >> 6) << 1);
    int tok = __ldg(&x[xrow]);
    const float* e0 = g_eproj + (size_t)tok * 768;
    float ez = __ldg(e0 + mycol);
    float er = __ldg(e0 + 256 + mycol);
    float eh = __ldg(e0 + 512 + mycol);
    int tok1 = __ldg(&x[xrow + 1]);

    for (int s = 0; s < SSZ; s++) {
        ull az0 = 0, az1 = 0, ar0 = 0, ar1 = 0;
        if (smw) {
#pragma unroll
            for (int kk = 0; kk < 32; kk++) {
                uint4 u = zsP[kk * 64];
                P1BODY(u, hb, kk);
            }
        } else {
#pragma unroll
            for (int kk = 0; kk < 32; kk++) {
                uint4 u = zr_ring[kk & 7];
                zr_ring[kk & 7] = zgP[((kk + 8) & 31) * 128];
                P1BODY(u, hb, kk);
            }
        }
        az0 = bflyadd(az0); az1 = bflyadd(az1);
        ar0 = bflyadd(ar0); ar1 = bflyadd(ar1);

        const float sz = pick(row ? az1 : az0, csel);
        const float sr = pick(row ? ar1 : ar0, csel);
        zg = fast_sigm(sz + ez);
        const float rg = fast_sigm(sr + er);
        const float rh = rg * hold;
        srhdup[wc] = pk2(rh, rh);
        const float* en = g_eproj + (size_t)tok1 * 768;
        ez = __ldg(en + mycol);
        er = __ldg(en + 256 + mycol);
        __syncthreads();

        ull ah0 = 0, ah1 = 0;
        if (smw) {
#pragma unroll
            for (int kk = 0; kk < 16; kk++) {
                uint4 u = hsP[kk * 64];
                P2BODY(u, hb, kk);
            }
        } else {
#pragma unroll
            for (int kk = 0; kk < 16; kk++) {
                uint4 u = uh_ring[kk & 3];
                uh_ring[kk & 3] = hgP[((kk + 4) & 15) * 128];
                P2BODY(u, hb, kk);
            }
        }
        ah0 = bflyadd(ah0); ah1 = bflyadd(ah1);

        const float sh = pick(row ? ah1 : ah0, csel);
        const float ht = fast_tanh(sh + eh);
        hold += zg * (ht - hold);
        hdup[wc] = pk2(hold, hold);
        eh = __ldg(en + 512 + mycol);
        {
            int s2 = (s + 2 < SSZ) ? s + 2 : SSZ - 1;
            tok1 = __ldg(&x[xrow + s2]);
        }
        __syncthreads();
    }

    g_hlast[(size_t)(b0 + row) * HSZ + mycol] = hold;
}

// ============================================================================
extern "C" void kernel_launch(void* const* d_in, const int* in_sizes, int n_in,
                              void* d_out, int out_size)
{
    const int*   x   = (const int*)  d_in[0];
    const float* emb = (const float*)d_in[1];
    const float* Wz  = (const float*)d_in[2];
    const float* bz  = (const float*)d_in[3];
    const float* Uz  = (const float*)d_in[4];
    const float* buz = (const float*)d_in[5];
    const float* Wr  = (const float*)d_in[6];
    const float* br  = (const float*)d_in[7];
    const float* Ur  = (const float*)d_in[8];
    const float* bur = (const float*)d_in[9];
    const float* Wh  = (const float*)d_in[10];
    const float* bh  = (const float*)d_in[11];
    const float* Uh  = (const float*)d_in[12];
    const float* buh = (const float*)d_in[13];
    const float* Wf  = (const float*)d_in[14];
    const float* bf  = (const float*)d_in[15];
    float* out = (float*)d_out;

    float *eproj, *bias768, *hlast;
    __nv_bfloat16 *emb_hi, *emb_lo, *w_hi, *w_lo;
    cudaGetSymbolAddress((void**)&eproj,   g_eproj);
    cudaGetSymbolAddress((void**)&bias768, g_bias768);
    cudaGetSymbolAddress((void**)&hlast,   g_hlast);
    cudaGetSymbolAddress((void**)&emb_hi,  g_emb_hi);
    cudaGetSymbolAddress((void**)&emb_lo,  g_emb_lo);
    cudaGetSymbolAddress((void**)&w_hi,    g_w_hi);
    cudaGetSymbolAddress((void**)&w_lo,    g_w_lo);

    cudaFuncSetAttribute(gru_scan16,
                         cudaFuncAttributeMaxDynamicSharedMemorySize, SCAN_SM_BYTES);
    cudaFuncSetAttribute(gemm_mma3,
                         cudaFuncAttributeMaxDynamicSharedMemorySize, GEMM_SMEM);

    pack_u<<<128, 128>>>(Uz, Ur, Uh);                                        // 0
    cvt_split<<<dim3(8000, 2), 1024>>>(emb, Wz, Wr, Wh,
                                       bz, buz, br, bur, bh, buh);           // 1
    gemm_mma3<<<dim3(250, 6), 256, GEMM_SMEM>>>(emb_hi, emb_lo, w_hi, w_lo,
                                                bias768, eproj, 768);        // 2
    shim_zero<<<256, 256>>>();                                               // 3
    shim_zero<<<256, 256>>>();                                               // 4
    gru_scan16<<<128, 512, SCAN_SM_BYTES>>>(x);                              // 5 <- ncu
    sgemm_nt_bias<<<dim3(2, 250), 256>>>(hlast, Wf, bf, out, 32000);         // 6
}

// round 17
// speedup vs baseline: 1.2584x; 1.0146x over previous
#include <cuda_runtime.h>
#include <cuda_bf16.h>
#include <cstdint>

#define VSZ 32000
#define HSZ 256
#define BSZ 256
#define SSZ 512

typedef unsigned long long ull;

// ---------------- device globals (no allocation allowed) ----------------
__device__ float g_eproj[(size_t)VSZ * 768];   // emb @ [Wz;Wr;Wh]^T + biases
__device__ float g_hlast[BSZ * HSZ];
// bf16 U streams for the scan (v8 layout)
__device__ uint4 g_zr4[128 * 128];
__device__ uint4 g_uh4[64 * 128];
// split-precision operands for the HMMA GEMMs (hi = bf16(x), lo = bf16(x-hi))
__device__ __nv_bfloat16 g_emb_hi[(size_t)VSZ * 256];
__device__ __nv_bfloat16 g_emb_lo[(size_t)VSZ * 256];
__device__ __nv_bfloat16 g_w_hi[768 * 256];
__device__ __nv_bfloat16 g_w_lo[768 * 256];
__device__ __nv_bfloat16 g_wf_hi[(size_t)VSZ * 256];
__device__ __nv_bfloat16 g_wf_lo[(size_t)VSZ * 256];
__device__ __nv_bfloat16 g_h_hi[BSZ * HSZ];
__device__ __nv_bfloat16 g_h_lo[BSZ * HSZ];
__device__ float g_bias768[768];

// ---------------- packed f32x2 helpers ----------------
__device__ __forceinline__ ull pk2(float lo, float hi) {
    ull r;
    asm("mov.b64 %0, {%1, %2};" : "=l"(r) : "f"(lo), "f"(hi));
    return r;
}
__device__ __forceinline__ void fma2(ull& d, ull a, ull b) {
    asm("fma.rn.f32x2 %0, %1, %2, %0;" : "+l"(d) : "l"(a), "l"(b));
}
__device__ __forceinline__ ull addf2(ull a, ull b) {
    ull r;
    asm("add.rn.f32x2 %0, %1, %2;" : "=l"(r) : "l"(a), "l"(b));
    return r;
}
__device__ __forceinline__ ull bflyadd(ull v) {
    v = addf2(v, __shfl_xor_sync(0xffffffffu, v, 8));
    v = addf2(v, __shfl_xor_sync(0xffffffffu, v, 16));
    return v;
}
__device__ __forceinline__ float pick(ull v, int hi_sel) {
    float lo, hi;
    asm("mov.b64 {%0, %1}, %2;" : "=f"(lo), "=f"(hi) : "l"(v));
    return hi_sel ? hi : lo;
}
__device__ __forceinline__ ull bf2f2(unsigned v) {
    ull r;
    asm("{\n\t.reg .b32 lo, hi;\n\t"
        "shl.b32 lo, %1, 16;\n\t"
        "and.b32 hi, %1, 0xFFFF0000;\n\t"
        "mov.b64 %0, {lo, hi};\n\t}" : "=l"(r) : "r"(v));
    return r;
}
__device__ __forceinline__ float fast_sigm(float x) {
    float e, r;
    asm("ex2.approx.ftz.f32 %0, %1;" : "=f"(e) : "f"(-1.4426950408889634f * x));
    asm("rcp.approx.ftz.f32 %0, %1;" : "=f"(r) : "f"(1.0f + e));
    return r;
}
__device__ __forceinline__ float fast_tanh(float x) {
    float r;
    asm("tanh.approx.f32 %0, %1;" : "=f"(r) : "f"(x));
    return r;
}
__device__ __forceinline__ unsigned pkbf(float lo, float hi) {
    unsigned short l = __bfloat16_as_ushort(__float2bfloat16(lo));
    unsigned short h = __bfloat16_as_ushort(__float2bfloat16(hi));
    return ((unsigned)h << 16) | (unsigned)l;
}
__device__ __forceinline__ uint32_t s2u(const void* p) {
    uint32_t a;
    asm("{ .reg .u64 t; cvta.to.shared.u64 t, %1; cvt.u32.u64 %0, t; }"
        : "=r"(a) : "l"(p));
    return a;
}
__device__ __forceinline__ void ldsm4(uint32_t& r0, uint32_t& r1,
                                      uint32_t& r2, uint32_t& r3, uint32_t addr) {
    asm volatile("ldmatrix.sync.aligned.m8n8.x4.shared.b16 {%0,%1,%2,%3}, [%4];"
                 : "=r"(r0), "=r"(r1), "=r"(r2), "=r"(r3) : "r"(addr));
}
__device__ __forceinline__ void mma16816(float* d, const uint32_t* a,
                                         const uint32_t* b) {
    asm volatile(
        "mma.sync.aligned.m16n8k16.row.col.f32.bf16.bf16.f32 "
        "{%0,%1,%2,%3}, {%4,%5,%6,%7}, {%8,%9}, {%0,%1,%2,%3};"
        : "+f"(d[0]), "+f"(d[1]), "+f"(d[2]), "+f"(d[3])
        : "r"(a[0]), "r"(a[1]), "r"(a[2]), "r"(a[3]), "r"(b[0]), "r"(b[1]));
}

// ============================================================================
// Pack U into transposed bf16 uint4 streams (scan operands)
// ============================================================================
__global__ void pack_u(const float* __restrict__ Uz, const float* __restrict__ Ur,
                       const float* __restrict__ Uh)
{
    const int k2 = blockIdx.x;
    const int jg = threadIdx.x;
    const int j0 = 2 * jg;
    const int ka = 2 * k2, kb = 2 * k2 + 1;
    uint4 v;
    v.x = pkbf(Uz[j0 * 256 + ka], Uz[(j0 + 1) * 256 + ka]);
    v.y = pkbf(Ur[j0 * 256 + ka], Ur[(j0 + 1) * 256 + ka]);
    v.z = pkbf(Uz[j0 * 256 + kb], Uz[(j0 + 1) * 256 + kb]);
    v.w = pkbf(Ur[j0 * 256 + kb], Ur[(j0 + 1) * 256 + kb]);
    g_zr4[k2 * 128 + jg] = v;
    if (k2 < 64) {
        const int kc = 4 * k2;
        uint4 h;
        h.x = pkbf(Uh[j0 * 256 + kc],     Uh[(j0 + 1) * 256 + kc]);
        h.y = pkbf(Uh[j0 * 256 + kc + 1], Uh[(j0 + 1) * 256 + kc + 1]);
        h.z = pkbf(Uh[j0 * 256 + kc + 2], Uh[(j0 + 1) * 256 + kc + 2]);
        h.w = pkbf(Uh[j0 * 256 + kc + 3], Uh[(j0 + 1) * 256 + kc + 3]);
        g_uh4[k2 * 128 + jg] = h;
    }
}

// ============================================================================
// fp32 -> split bf16 hi/lo (emb, [Wz;Wr;Wh], Wf) + bias pre-sum
// ============================================================================
__global__ void cvt_split(const float* __restrict__ emb,
                          const float* __restrict__ Wz, const float* __restrict__ Wr,
                          const float* __restrict__ Wh, const float* __restrict__ Wf,
                          const float* __restrict__ bz, const float* __restrict__ buz,
                          const float* __restrict__ br, const float* __restrict__ bur,
                          const float* __restrict__ bh, const float* __restrict__ buh)
{
    const size_t idx = (size_t)blockIdx.x * 1024 + threadIdx.x;
    if (blockIdx.y == 0) {
        float v = emb[idx];
        __nv_bfloat16 h = __float2bfloat16(v);
        g_emb_hi[idx] = h;
        g_emb_lo[idx] = __float2bfloat16(v - __bfloat162float(h));
    } else if (blockIdx.y == 1) {
        float v = Wf[idx];
        __nv_bfloat16 h = __float2bfloat16(v);
        g_wf_hi[idx] = h;
        g_wf_lo[idx] = __float2bfloat16(v - __bfloat162float(h));
    } else {
        if (idx < 196608) {
            float v = (idx < 65536) ? Wz[idx]
                    : (idx < 131072) ? Wr[idx - 65536]
                                     : Wh[idx - 131072];
            __nv_bfloat16 h = __float2bfloat16(v);
            g_w_hi[idx] = h;
            g_w_lo[idx] = __float2bfloat16(v - __bfloat162float(h));
        }
        if (idx < 768) {
            int g = (int)(idx >> 8), j = (int)(idx & 255);
            g_bias768[idx] = (g == 0) ? bz[j] + buz[j]
                           : (g == 1) ? br[j] + bur[j]
                                      : bh[j] + buh[j];
        }
    }
}

__global__ void cvt_hsplit()
{
    int i = blockIdx.x * 1024 + threadIdx.x;
    float v = g_hlast[i];
    __nv_bfloat16 h = __float2bfloat16(v);
    g_h_hi[i] = h;
    g_h_lo[i] = __float2bfloat16(v - __bfloat162float(h));
}

__global__ void shim_zero()
{
    g_hlast[blockIdx.x * 256 + threadIdx.x] = 0.0f;
}

// ============================================================================
// Split-precision HMMA GEMM (NT): D = (Ah+Al)@(Bh+Bl)^T + bias via
// Ah.Bh + Ah.Bl + Al.Bh (Al.Bl ~2^-18 dropped) -> fp32-equivalent accuracy.
// Validated round 16 (rel_err unchanged vs full-scalar pipeline).
// ============================================================================
#define GS2 136
#define GEMM_SMEM (4 * 128 * GS2 * 2)   // 139264 B

__global__ void __launch_bounds__(256) gemm_mma3(
    const __nv_bfloat16* __restrict__ Ah, const __nv_bfloat16* __restrict__ Al,
    const __nv_bfloat16* __restrict__ Bh, const __nv_bfloat16* __restrict__ Bl,
    const float* __restrict__ bias, float* __restrict__ C, int ldc)
{
    extern __shared__ __align__(16) char sm[];
    __nv_bfloat16* sAh = (__nv_bfloat16*)sm;
    __nv_bfloat16* sAl = sAh + 128 * GS2;
    __nv_bfloat16* sBh = sAl + 128 * GS2;
    __nv_bfloat16* sBl = sBh + 128 * GS2;

    const int t = threadIdx.x, w = t >> 5, lane = t & 31;
    const int wm = w & 3, wn = w >> 2;
    const int r = lane & 7, sel = lane >> 3;

    uint32_t aRel[2], bRel[4];
#pragma unroll
    for (int mi = 0; mi < 2; mi++) {
        int row = wm * 32 + mi * 16 + (sel & 1) * 8 + r;
        aRel[mi] = (uint32_t)(row * GS2 + (sel >> 1) * 8) * 2;
    }
#pragma unroll
    for (int nq = 0; nq < 4; nq++) {
        int row = wn * 64 + nq * 16 + (sel >> 1) * 8 + r;
        bRel[nq] = (uint32_t)(row * GS2 + (sel & 1) * 8) * 2;
    }
    const uint32_t sah = s2u(sAh), sal = s2u(sAl);
    const uint32_t sbh = s2u(sBh), sbl = s2u(sBl);

    float acc[2][8][4];
#pragma unroll
    for (int mi = 0; mi < 2; mi++)
#pragma unroll
        for (int ni = 0; ni < 8; ni++)
#pragma unroll
            for (int c = 0; c < 4; c++) acc[mi][ni][c] = 0.0f;

    const size_t aBase = (size_t)blockIdx.x * 128 * 256;
    const size_t bBase = (size_t)blockIdx.y * 128 * 256;

    for (int kc = 0; kc < 2; kc++) {
        if (kc) __syncthreads();
        const uint4* Ahg = (const uint4*)(Ah + aBase) + kc * 16;
        const uint4* Alg = (const uint4*)(Al + aBase) + kc * 16;
        const uint4* Bhg = (const uint4*)(Bh + bBase) + kc * 16;
        const uint4* Blg = (const uint4*)(Bl + bBase) + kc * 16;
        for (int i = t; i < 2048; i += 256) {
            int row = i >> 4, q = i & 15;
            size_t g = (size_t)row * 32 + q;
            uint32_t so = (uint32_t)(row * GS2 + q * 8);
            *(uint4*)(sAh + so) = Ahg[g];
            *(uint4*)(sAl + so) = Alg[g];
            *(uint4*)(sBh + so) = Bhg[g];
            *(uint4*)(sBl + so) = Blg[g];
        }
        __syncthreads();

#pragma unroll
        for (int ks = 0; ks < 8; ks++) {
            const uint32_t kb = (uint32_t)(ks * 32);
            uint32_t afh[2][4], afl[2][4], bfh[8][2], bfl[8][2];
#pragma unroll
            for (int mi = 0; mi < 2; mi++) {
                ldsm4(afh[mi][0], afh[mi][1], afh[mi][2], afh[mi][3],
                      sah + aRel[mi] + kb);
                ldsm4(afl[mi][0], afl[mi][1], afl[mi][2], afl[mi][3],
                      sal + aRel[mi] + kb);
            }
#pragma unroll
            for (int nq = 0; nq < 4; nq++) {
                uint32_t b0, b1, b2, b3;
                ldsm4(b0, b1, b2, b3, sbh + bRel[nq] + kb);
                bfh[2 * nq][0] = b0;     bfh[2 * nq][1] = b1;
                bfh[2 * nq + 1][0] = b2; bfh[2 * nq + 1][1] = b3;
                ldsm4(b0, b1, b2, b3, sbl + bRel[nq] + kb);
                bfl[2 * nq][0] = b0;     bfl[2 * nq][1] = b1;
                bfl[2 * nq + 1][0] = b2; bfl[2 * nq + 1][1] = b3;
            }
#pragma unroll
            for (int mi = 0; mi < 2; mi++)
#pragma unroll
                for (int ni = 0; ni < 8; ni++) {
                    mma16816(acc[mi][ni], afh[mi], bfh[ni]);
                    mma16816(acc[mi][ni], afh[mi], bfl[ni]);
                    mma16816(acc[mi][ni], afl[mi], bfh[ni]);
                }
        }
    }

    const int co = blockIdx.y * 128;
    const int rbase = blockIdx.x * 128 + wm * 32 + (lane >> 2);
    const int cb = wn * 64 + (lane & 3) * 2;
#pragma unroll
    for (int mi = 0; mi < 2; mi++) {
#pragma unroll
        for (int half = 0; half < 2; half++) {
            const int grow = rbase + mi * 16 + half * 8;
            float* cp = C + (size_t)grow * ldc + co;
#pragma unroll
            for (int ni = 0; ni < 8; ni++) {
                const int col = cb + ni * 8;
                float2 v;
                v.x = acc[mi][ni][half * 2]     + bias[co + col];
                v.y = acc[mi][ni][half * 2 + 1] + bias[co + col + 1];
                *(float2*)(cp + col) = v;
            }
        }
    }
}

// ============================================================================
// GRU scan: EXACT v8. Untouched.
// ============================================================================
#define SCAN_SM_BYTES 204928

#define P1BODY(u, hb, kk)                                                   \
    {                                                                       \
        ull uz0 = bf2f2((u).x), ur0 = bf2f2((u).y);                         \
        ull uz1 = bf2f2((u).z), ur1 = bf2f2((u).w);                         \
        ulonglong2 h0 = *(const ulonglong2*)(hdup + (hb) + 4 * (kk));       \
        ulonglong2 h1 = *(const ulonglong2*)(hdup + (hb) + 4 * (kk) + 2);   \
        fma2(az0, uz0, h0.x); fma2(az1, uz0, h0.y);                         \
        fma2(ar0, ur0, h0.x); fma2(ar1, ur0, h0.y);                         \
        fma2(az0, uz1, h1.x); fma2(az1, uz1, h1.y);                         \
        fma2(ar0, ur1, h1.x); fma2(ar1, ur1, h1.y);                         \
    }

#define P2BODY(u, sb, kk)                                                   \
    {                                                                       \
        ull uh0 = bf2f2((u).x), uh1 = bf2f2((u).y);                         \
        ull uh2 = bf2f2((u).z), uh3 = bf2f2((u).w);                         \
        ulonglong2 s0 = *(const ulonglong2*)(srhdup + (sb) + 8 * (kk));     \
        ulonglong2 s1 = *(const ulonglong2*)(srhdup + (sb) + 8 * (kk) + 2); \
        ulonglong2 s2 = *(const ulonglong2*)(srhdup + (sb) + 8 * (kk) + 4); \
        ulonglong2 s3 = *(const ulonglong2*)(srhdup + (sb) + 8 * (kk) + 6); \
        fma2(ah0, uh0, s0.x); fma2(ah1, uh0, s0.y);                         \
        fma2(ah0, uh1, s1.x); fma2(ah1, uh1, s1.y);                         \
        fma2(ah0, uh2, s2.x); fma2(ah1, uh2, s2.y);                         \
        fma2(ah0, uh3, s3.x); fma2(ah1, uh3, s3.y);                         \
    }

__global__ void __launch_bounds__(512, 1) gru_scan17(const int* __restrict__ x)
{
    extern __shared__ __align__(16) char smraw[];
    uint4* pin_zr4 = (uint4*)smraw;
    uint4* pin_uh4 = (uint4*)(smraw + 131072);
    ull*   hdup    = (ull*)(smraw + 196608);
    ull*   srhdup  = (ull*)(smraw + 200768);

    const int t    = threadIdx.x;
    const int lane = t & 31;
    const int w    = t >> 5;
    const int jp   = (w << 3) | (lane & 7);
    const int kh   = lane >> 3;
    const int row  = kh & 1;
    const int csel = kh >> 1;
    const int mycol = (jp << 1) | csel;
    const int b0   = blockIdx.x * 2;
    const bool smw = (w < 8);

    for (int i = t; i < 128 * 64; i += 512)
        pin_zr4[i] = g_zr4[(i >> 6) * 128 + (i & 63)];
    for (int i = t; i < 64 * 64; i += 512)
        pin_uh4[i] = g_uh4[(i >> 6) * 128 + (i & 63)];
    for (int i = t; i < 520; i += 512) { hdup[i] = 0ULL; srhdup[i] = 0ULL; }
    __syncthreads();

    const uint4* zsP = pin_zr4 + (kh * 32) * 64 + jp;
    const uint4* zgP = g_zr4   + (kh * 32) * 128 + jp;
    const uint4* hsP = pin_uh4 + (kh * 16) * 64 + jp;
    const uint4* hgP = g_uh4   + (kh * 16) * 128 + jp;
    const int hb = 130 * kh;

    uint4 zr_ring[8], uh_ring[4];
    if (!smw) {
#pragma unroll
        for (int i = 0; i < 8; i++) zr_ring[i] = zgP[i * 128];
#pragma unroll
        for (int i = 0; i < 4; i++) uh_ring[i] = hgP[i * 128];
    }

    float hold = 0.0f, zg = 0.0f;
    const int xrow = (b0 + row) * SSZ;
    const int wc = 2 * mycol + row + ((mycol >> 6) << 1);
    int tok = __ldg(&x[xrow]);
    const float* e0 = g_eproj + (size_t)tok * 768;
    float ez = __ldg(e0 + mycol);
    float er = __ldg(e0 + 256 + mycol);
    float eh = __ldg(e0 + 512 + mycol);
    int tok1 = __ldg(&x[xrow + 1]);

    for (int s = 0; s < SSZ; s++) {
        ull az0 = 0, az1 = 0, ar0 = 0, ar1 = 0;
        if (smw) {
#pragma unroll
            for (int kk = 0; kk < 32; kk++) {
                uint4 u = zsP[kk * 64];
                P1BODY(u, hb, kk);
            }
        } else {
#pragma unroll
            for (int kk = 0; kk < 32; kk++) {
                uint4 u = zr_ring[kk & 7];
                zr_ring[kk & 7] = zgP[((kk + 8) & 31) * 128];
                P1BODY(u, hb, kk);
            }
        }
        az0 = bflyadd(az0); az1 = bflyadd(az1);
        ar0 = bflyadd(ar0); ar1 = bflyadd(ar1);

        const float sz = pick(row ? az1 : az0, csel);
        const float sr = pick(row ? ar1 : ar0, csel);
        zg = fast_sigm(sz + ez);
        const float rg = fast_sigm(sr + er);
        const float rh = rg * hold;
        srhdup[wc] = pk2(rh, rh);
        const float* en = g_eproj + (size_t)tok1 * 768;
        ez = __ldg(en + mycol);
        er = __ldg(en + 256 + mycol);
        __syncthreads();

        ull ah0 = 0, ah1 = 0;
        if (smw) {
#pragma unroll
            for (int kk = 0; kk < 16; kk++) {
                uint4 u = hsP[kk * 64];
                P2BODY(u, hb, kk);
            }
        } else {
#pragma unroll
            for (int kk = 0; kk < 16; kk++) {
                uint4 u = uh_ring[kk & 3];
                uh_ring[kk & 3] = hgP[((kk + 4) & 15) * 128];
                P2BODY(u, hb, kk);
            }
        }
        ah0 = bflyadd(ah0); ah1 = bflyadd(ah1);

        const float sh = pick(row ? ah1 : ah0, csel);
        const float ht = fast_tanh(sh + eh);
        hold += zg * (ht - hold);
        hdup[wc] = pk2(hold, hold);
        eh = __ldg(en + 512 + mycol);
        {
            int s2 = (s + 2 < SSZ) ? s + 2 : SSZ - 1;
            tok1 = __ldg(&x[xrow + s2]);
        }
        __syncthreads();
    }

    g_hlast[(size_t)(b0 + row) * HSZ + mycol] = hold;
}

// ============================================================================
extern "C" void kernel_launch(void* const* d_in, const int* in_sizes, int n_in,
                              void* d_out, int out_size)
{
    const int*   x   = (const int*)  d_in[0];
    const float* emb = (const float*)d_in[1];
    const float* Wz  = (const float*)d_in[2];
    const float* bz  = (const float*)d_in[3];
    const float* Uz  = (const float*)d_in[4];
    const float* buz = (const float*)d_in[5];
    const float* Wr  = (const float*)d_in[6];
    const float* br  = (const float*)d_in[7];
    const float* Ur  = (const float*)d_in[8];
    const float* bur = (const float*)d_in[9];
    const float* Wh  = (const float*)d_in[10];
    const float* bh  = (const float*)d_in[11];
    const float* Uh  = (const float*)d_in[12];
    const float* buh = (const float*)d_in[13];
    const float* Wf  = (const float*)d_in[14];
    const float* bf  = (const float*)d_in[15];
    float* out = (float*)d_out;

    float *eproj, *bias768;
    __nv_bfloat16 *emb_hi, *emb_lo, *w_hi, *w_lo, *wf_hi, *wf_lo, *h_hi, *h_lo;
    cudaGetSymbolAddress((void**)&eproj,   g_eproj);
    cudaGetSymbolAddress((void**)&bias768, g_bias768);
    cudaGetSymbolAddress((void**)&emb_hi,  g_emb_hi);
    cudaGetSymbolAddress((void**)&emb_lo,  g_emb_lo);
    cudaGetSymbolAddress((void**)&w_hi,    g_w_hi);
    cudaGetSymbolAddress((void**)&w_lo,    g_w_lo);
    cudaGetSymbolAddress((void**)&wf_hi,   g_wf_hi);
    cudaGetSymbolAddress((void**)&wf_lo,   g_wf_lo);
    cudaGetSymbolAddress((void**)&h_hi,    g_h_hi);
    cudaGetSymbolAddress((void**)&h_lo,    g_h_lo);

    cudaFuncSetAttribute(gru_scan17,
                         cudaFuncAttributeMaxDynamicSharedMemorySize, SCAN_SM_BYTES);
    cudaFuncSetAttribute(gemm_mma3,
                         cudaFuncAttributeMaxDynamicSharedMemorySize, GEMM_SMEM);

    pack_u<<<128, 128>>>(Uz, Ur, Uh);                                        // 0
    cvt_split<<<dim3(8000, 3), 1024>>>(emb, Wz, Wr, Wh, Wf,
                                       bz, buz, br, bur, bh, buh);           // 1
    gemm_mma3<<<dim3(250, 6), 256, GEMM_SMEM>>>(emb_hi, emb_lo, w_hi, w_lo,
                                                bias768, eproj, 768);        // 2
    shim_zero<<<256, 256>>>();                                               // 3
    shim_zero<<<256, 256>>>();                                               // 4
    gru_scan17<<<128, 512, SCAN_SM_BYTES>>>(x);                              // 5 <- ncu
    cvt_hsplit<<<64, 1024>>>();                                              // 6
    gemm_mma3<<<dim3(2, 250), 256, GEMM_SMEM>>>(h_hi, h_lo, wf_hi, wf_lo,
                                                bf, out, 32000);             // 7
}